// round 1
// baseline (speedup 1.0000x reference)
#include <cuda_runtime.h>
#include <math.h>

// ---------------- problem constants ----------------
#define BB 4
#define SS 512
#define DD 1024
#define HH 16
#define DHD 64
#define DQ 256
#define NTOK (BB*SS)            // 2048
#define BHN (BB*HH)             // 64
#define MIN_STEPS 4
#define MAX_STEPS 12

// ---------------- device state ----------------
__device__ int    g_act;
__device__ int    g_active;
__device__ int    g_num_steps;
__device__ float  g_gw0;
__device__ double g_red[2];

__device__ float g_h    [NTOK*DD];
__device__ float g_hnew [NTOK*DD];
__device__ float g_T1   [NTOK*DQ];
__device__ float g_G1   [NTOK*DD];
__device__ float g_T2   [NTOK*DQ];
__device__ float g_blend[NTOK*DD];
__device__ float g_wqkv [3*DD*DD];
__device__ float g_bqkv [3*DD];
__device__ float g_qkv  [NTOK*3*DD];
__device__ float g_q    [BHN*SS*DHD];
__device__ float g_k    [BHN*SS*DHD];
__device__ float g_vT   [BHN*DHD*SS];
__device__ float g_sc   [BHN*SS*SS];      // 64 MB scores scratch
__device__ float g_ctx  [BHN*SS*DHD];
__device__ float g_ctxr [NTOK*DD];
__device__ float g_phi  [NTOK*DD];
__device__ float g_pool [BB*DD];
__device__ float g_sph  [BB*DQ];

// ---------------- helpers ----------------
__device__ __forceinline__ float gelu_f(float v){ return 0.5f*v*(1.0f+erff(v*0.70710678118654752f)); }
__device__ __forceinline__ float sig_f (float v){ return 1.0f/(1.0f+__expf(-v)); }

template<typename T>
__device__ __forceinline__ T blockReduceSum(T v){
    static __shared__ T sh[32];
    int lane = threadIdx.x & 31, w = threadIdx.x >> 5;
    #pragma unroll
    for (int o = 16; o; o >>= 1) v += __shfl_down_sync(0xffffffffu, v, o);
    __syncthreads();                 // protect sh reuse across calls
    if (lane == 0) sh[w] = v;
    __syncthreads();
    T r = (T)0;
    if (w == 0){
        int nw = (blockDim.x + 31) >> 5;
        r = (lane < nw) ? sh[lane] : (T)0;
        #pragma unroll
        for (int o = 16; o; o >>= 1) r += __shfl_down_sync(0xffffffffu, r, o);
    }
    return r;   // valid at thread 0
}

// ---------------- generic NT SGEMM with fused epilogues ----------------
// C[bz](m,n) = epi( alpha * sum_k A(m,k)*B(n,k) [+ C_old if ACC] [+ bias[n]] )
enum { EPI_NONE=0, EPI_GELU=1, EPI_SIG=2, EPI_BLEND=3, EPI_GSCALE=4 };

template<int BM,int BN,int BK,int TM,int TN,int EPI,bool ACC>
__global__ void __launch_bounds__((BM/TM)*(BN/TN))
gemm_nt(int M,int N,int K,
        const float* __restrict__ A,int lda,long long sA,
        const float* __restrict__ B,int ldb,long long sB,
        float* __restrict__ C,int ldc,long long sC,
        const float* __restrict__ bias,float alpha,
        const float* __restrict__ Hp,const float* __restrict__ Xp)
{
    if (g_act == 0) return;
    constexpr int NT = (BM/TM)*(BN/TN);
    const int tid = threadIdx.x;
    const int bz  = blockIdx.z;
    A += (long long)bz * sA;
    B += (long long)bz * sB;
    C += (long long)bz * sC;

    __shared__ float As[BK][BM+4];
    __shared__ float Bs[BK][BN+4];

    const int tx = tid % (BN/TN);
    const int ty = tid / (BN/TN);
    const int rm = blockIdx.y * BM;
    const int cn = blockIdx.x * BN;

    float acc[TM][TN];
    #pragma unroll
    for (int i=0;i<TM;i++)
        #pragma unroll
        for (int j=0;j<TN;j++) acc[i][j]=0.0f;

    constexpr int A4 = BM*BK/4/NT;
    constexpr int B4 = BN*BK/4/NT;

    for (int kt = 0; kt < K; kt += BK){
        #pragma unroll
        for (int it=0; it<A4; it++){
            int idx = tid + it*NT;
            int row = idx / (BK/4);
            int kc  = (idx % (BK/4)) * 4;
            float4 v = *(const float4*)&A[(long long)(rm+row)*lda + kt + kc];
            As[kc+0][row]=v.x; As[kc+1][row]=v.y; As[kc+2][row]=v.z; As[kc+3][row]=v.w;
        }
        #pragma unroll
        for (int it=0; it<B4; it++){
            int idx = tid + it*NT;
            int row = idx / (BK/4);
            int kc  = (idx % (BK/4)) * 4;
            float4 v = *(const float4*)&B[(long long)(cn+row)*ldb + kt + kc];
            Bs[kc+0][row]=v.x; Bs[kc+1][row]=v.y; Bs[kc+2][row]=v.z; Bs[kc+3][row]=v.w;
        }
        __syncthreads();
        #pragma unroll
        for (int kk=0; kk<BK; kk++){
            float a[TM], b[TN];
            #pragma unroll
            for (int i=0;i<TM;i++) a[i]=As[kk][ty*TM+i];
            #pragma unroll
            for (int j=0;j<TN;j++) b[j]=Bs[kk][tx*TN+j];
            #pragma unroll
            for (int i=0;i<TM;i++)
                #pragma unroll
                for (int j=0;j<TN;j++) acc[i][j] = fmaf(a[i], b[j], acc[i][j]);
        }
        __syncthreads();
    }

    #pragma unroll
    for (int i=0;i<TM;i++){
        int r = rm + ty*TM + i;
        #pragma unroll
        for (int j=0;j<TN;j++){
            int c = cn + tx*TN + j;
            long long gi = (long long)r*ldc + c;
            float v = acc[i][j]*alpha;
            if (ACC) v += C[gi];
            if (bias) v += bias[c];
            if      (EPI==EPI_GELU)   v = gelu_f(v);
            else if (EPI==EPI_SIG)    v = sig_f(v);
            else if (EPI==EPI_GSCALE) v = sig_f(v) * g_gw0;
            else if (EPI==EPI_BLEND){
                float s = sig_f(v);
                v = s*Hp[gi] + (1.0f - s)*Xp[gi];
            }
            C[gi] = v;
        }
    }
}

// ---------------- small kernels ----------------
__global__ void k_copy(const float* __restrict__ s, float* __restrict__ d, long long n){
    long long i = (long long)blockIdx.x*blockDim.x + threadIdx.x;
    if (i < n) d[i] = s[i];
}

__global__ void k_pool(const float* __restrict__ h){
    int i = blockIdx.x*blockDim.x + threadIdx.x;        // [0, BB*DD)
    if (i >= BB*DD) return;
    int b = i / DD, d = i % DD;
    const float* p = h + (long long)b*SS*DD + d;
    float s = 0.0f;
    for (int t=0;t<SS;t++) s += p[(long long)t*DD];
    g_pool[i] = s * (1.0f/(float)SS);
}

__global__ void k_sp1(const float* __restrict__ w1, const float* __restrict__ b1){
    int i = blockIdx.x*blockDim.x + threadIdx.x;        // [0, BB*DQ)
    if (i >= BB*DQ) return;
    int b = i / DQ, j = i % DQ;
    const float* p = g_pool + b*DD;
    const float* w = w1 + (long long)j*DD;
    float s = b1[j];
    for (int d=0; d<DD; d++) s = fmaf(p[d], w[d], s);
    g_sph[i] = gelu_f(s);
}

__global__ void k_init(const float* __restrict__ w2, const float* __restrict__ b2,
                       const float* __restrict__ gl){
    if (threadIdx.x != 0) return;
    float m = 0.0f;
    for (int b=0;b<BB;b++){
        float s = b2[0];
        for (int j=0;j<DQ;j++) s = fmaf(g_sph[b*DQ+j], w2[j], s);
        m += 1.0f/(1.0f + expf(-s));
    }
    m *= 1.0f/(float)BB;
    int ns = MIN_STEPS + (int)floorf(m * (float)(MAX_STEPS - MIN_STEPS));
    if (ns > MAX_STEPS) ns = MAX_STEPS;
    g_num_steps = ns;
    g_active = 1;
    float e0 = expf(gl[0]), e1 = expf(gl[1]), e2 = expf(gl[2]);
    g_gw0 = e0/(e0+e1+e2);
}

__global__ void k_begin(int i){
    if (threadIdx.x == 0){
        g_act = (g_active && (i < g_num_steps)) ? 1 : 0;
        g_red[0] = 0.0; g_red[1] = 0.0;
    }
}

__global__ void k_qkv_split(void){
    if (g_act == 0) return;
    long long i = (long long)blockIdx.x*blockDim.x + threadIdx.x;   // [0, NTOK*3*DD)
    int t = (int)(i / (3*DD)), n = (int)(i % (3*DD));
    int which = n >> 10, w = n & 1023;
    int hh = w >> 6, dh = w & 63;
    int b = t >> 9, s = t & 511;
    int bh = b*HH + hh;
    float v = g_qkv[i];
    if      (which == 0) g_q [((long long)bh*SS + s)*DHD + dh] = v;
    else if (which == 1) g_k [((long long)bh*SS + s)*DHD + dh] = v;
    else                 g_vT[((long long)bh*DHD + dh)*SS + s] = v;
}

__global__ void k_softmax(void){
    if (g_act == 0) return;
    float* row = g_sc + (long long)blockIdx.x * SS;
    int t = threadIdx.x;                       // 128 threads, 4 values each
    float v0=row[t], v1=row[t+128], v2=row[t+256], v3=row[t+384];
    float mx = fmaxf(fmaxf(v0,v1), fmaxf(v2,v3));
    #pragma unroll
    for (int o=16;o;o>>=1) mx = fmaxf(mx, __shfl_xor_sync(0xffffffffu, mx, o));
    __shared__ float sm[4];
    if ((t&31)==0) sm[t>>5] = mx;
    __syncthreads();
    mx = fmaxf(fmaxf(sm[0],sm[1]), fmaxf(sm[2],sm[3]));
    v0 = __expf(v0-mx); v1 = __expf(v1-mx); v2 = __expf(v2-mx); v3 = __expf(v3-mx);
    float s = v0+v1+v2+v3;
    #pragma unroll
    for (int o=16;o;o>>=1) s += __shfl_xor_sync(0xffffffffu, s, o);
    __shared__ float sq[4];
    if ((t&31)==0) sq[t>>5] = s;
    __syncthreads();
    s = sq[0]+sq[1]+sq[2]+sq[3];
    float inv = 1.0f/s;
    row[t]=v0*inv; row[t+128]=v1*inv; row[t+256]=v2*inv; row[t+384]=v3*inv;
}

__global__ void k_ctx_r(void){
    if (g_act == 0) return;
    long long i = (long long)blockIdx.x*blockDim.x + threadIdx.x;   // [0, NTOK*DD)
    int t = (int)(i / DD), d = (int)(i % DD);
    int b = t >> 9, s = t & 511;
    int hh = d >> 6, dh = d & 63;
    g_ctxr[i] = g_ctx[(((long long)(b*HH+hh))*SS + s)*DHD + dh];
}

__global__ void k_ln(const float* __restrict__ lg, const float* __restrict__ lb){
    if (g_act == 0) return;
    long long off = (long long)blockIdx.x * DD;
    int t = threadIdx.x;                      // 256 threads, 4 elements each
    float u[4], hv[4];
    float sm = 0.0f;
    #pragma unroll
    for (int j=0;j<4;j++){
        int idx = t + j*256;
        hv[j] = g_h[off+idx];
        u[j]  = fmaf(g_G1[off+idx], g_phi[off+idx], hv[j]);
        sm += u[j];
    }
    sm = blockReduceSum<float>(sm);
    __shared__ float s_mean, s_inv;
    if (t==0) s_mean = sm * (1.0f/(float)DD);
    __syncthreads();
    float mean = s_mean, vs = 0.0f;
    #pragma unroll
    for (int j=0;j<4;j++){ float d = u[j]-mean; vs += d*d; }
    vs = blockReduceSum<float>(vs);
    if (t==0) s_inv = rsqrtf(vs*(1.0f/(float)DD) + 1e-5f);
    __syncthreads();
    float inv = s_inv;
    double dq = 0.0, hq = 0.0;
    #pragma unroll
    for (int j=0;j<4;j++){
        int idx = t + j*256;
        float y = (u[j]-mean)*inv*lg[idx] + lb[idx];
        g_hnew[off+idx] = y;
        float df = y - hv[j];
        dq += (double)df*(double)df;
        hq += (double)hv[j]*(double)hv[j];
    }
    dq = blockReduceSum<double>(dq);
    hq = blockReduceSum<double>(hq);
    if (t==0){ atomicAdd(&g_red[0], dq); atomicAdd(&g_red[1], hq); }
}

__global__ void k_fin(int i){
    if (threadIdx.x != 0) return;
    if (g_act == 0){ g_active = 0; return; }
    double res = sqrt(g_red[0]) / (sqrt(g_red[1]) + 1e-8);
    g_active = ((i >= MIN_STEPS) && (res < 1e-4)) ? 0 : 1;
}

__global__ void k_commit(void){
    if (g_act == 0) return;
    long long i = (long long)blockIdx.x*blockDim.x + threadIdx.x;
    g_h[i] = g_hnew[i];
}

// ---------------- host ----------------
static float* dptr(const void* symbol){
    void* p = nullptr;
    cudaGetSymbolAddress(&p, symbol);
    return (float*)p;
}

extern "C" void kernel_launch(void* const* d_in, const int* in_sizes, int n_in,
                              void* d_out, int out_size)
{
    const float* h     = (const float*)d_in[0];
    const float* x     = (const float*)d_in[1];
    const float* ig_w1 = (const float*)d_in[2];
    const float* ig_b1 = (const float*)d_in[3];
    const float* ig_w2 = (const float*)d_in[4];
    const float* ig_b2 = (const float*)d_in[5];
    const float* wq    = (const float*)d_in[6];
    const float* bq    = (const float*)d_in[7];
    const float* wk    = (const float*)d_in[8];
    const float* bk    = (const float*)d_in[9];
    const float* wv    = (const float*)d_in[10];
    const float* bv    = (const float*)d_in[11];
    const float* wo    = (const float*)d_in[12];
    const float* bo    = (const float*)d_in[13];
    const float* g1w1  = (const float*)d_in[14];
    const float* g1b1  = (const float*)d_in[15];
    const float* g1w2  = (const float*)d_in[16];
    const float* g1b2  = (const float*)d_in[17];
    const float* gl    = (const float*)d_in[18];
    const float* lng   = (const float*)d_in[19];
    const float* lnb   = (const float*)d_in[20];
    const float* spw1  = (const float*)d_in[21];
    const float* spb1  = (const float*)d_in[22];
    const float* spw2  = (const float*)d_in[23];
    const float* spb2  = (const float*)d_in[24];
    float* out = (float*)d_out;

    float* p_h     = dptr(g_h);
    float* p_hnew  = dptr(g_hnew);
    float* p_T1    = dptr(g_T1);
    float* p_G1    = dptr(g_G1);
    float* p_T2    = dptr(g_T2);
    float* p_blend = dptr(g_blend);
    float* p_wqkv  = dptr(g_wqkv);
    float* p_bqkv  = dptr(g_bqkv);
    float* p_qkv   = dptr(g_qkv);
    float* p_q     = dptr(g_q);
    float* p_k     = dptr(g_k);
    float* p_vT    = dptr(g_vT);
    float* p_sc    = dptr(g_sc);
    float* p_ctx   = dptr(g_ctx);
    float* p_ctxr  = dptr(g_ctxr);
    float* p_phi   = dptr(g_phi);

    const long long NHD = (long long)NTOK*DD;     // 2097152
    const long long W1  = (long long)DD*DD;       // 1048576

    // one-time-per-launch setup (inside capture; cheap)
    k_copy<<<(unsigned)((NHD+255)/256),256>>>(h,  p_h, NHD);
    k_copy<<<(unsigned)((W1+255)/256),256>>>(wq, p_wqkv,        W1);
    k_copy<<<(unsigned)((W1+255)/256),256>>>(wk, p_wqkv +   W1, W1);
    k_copy<<<(unsigned)((W1+255)/256),256>>>(wv, p_wqkv + 2*W1, W1);
    k_copy<<<4,256>>>(bq, p_bqkv,        DD);
    k_copy<<<4,256>>>(bk, p_bqkv +   DD, DD);
    k_copy<<<4,256>>>(bv, p_bqkv + 2*DD, DD);
    k_pool<<<(BB*DD+255)/256,256>>>(h);
    k_sp1 <<<(BB*DQ+255)/256,256>>>(spw1, spb1);
    k_init<<<1,32>>>(spw2, spb2, gl);

    const float scale = 0.125f;   // 1/sqrt(64)

    for (int i = 0; i < MAX_STEPS; i++){
        k_begin<<<1,32>>>(i);

        // T1 = gelu(h @ g1_w1^T + g1_b1)                 (2048 x 256, K=1024)
        gemm_nt<64,64,16,4,4,EPI_GELU,false><<<dim3(4,32,1),256>>>(
            NTOK, DQ, DD, p_h, DD, 0, g1w1, DD, 0, p_T1, DQ, 0, g1b1, 1.0f, nullptr, nullptr);

        // G1 = sigmoid(T1 @ g1_w2^T + g1_b2) * gw0       (2048 x 1024, K=256)
        gemm_nt<128,128,16,8,8,EPI_GSCALE,false><<<dim3(8,16,1),256>>>(
            NTOK, DD, DQ, p_T1, DQ, 0, g1w2, DQ, 0, p_G1, DD, 0, g1b2, 1.0f, nullptr, nullptr);

        // T2 = gelu(h @ ig_w1[:, :D]^T + x @ ig_w1[:, D:]^T + ig_b1)
        gemm_nt<64,64,16,4,4,EPI_NONE,false><<<dim3(4,32,1),256>>>(
            NTOK, DQ, DD, p_h, DD, 0, ig_w1, 2*DD, 0, p_T2, DQ, 0, nullptr, 1.0f, nullptr, nullptr);
        gemm_nt<64,64,16,4,4,EPI_GELU,true><<<dim3(4,32,1),256>>>(
            NTOK, DQ, DD, x, DD, 0, ig_w1 + DD, 2*DD, 0, p_T2, DQ, 0, ig_b1, 1.0f, nullptr, nullptr);

        // blended = sigmoid(T2 @ ig_w2^T + ig_b2)*h + (1-.)*x   (2048 x 1024, K=256)
        gemm_nt<128,128,16,8,8,EPI_BLEND,false><<<dim3(8,16,1),256>>>(
            NTOK, DD, DQ, p_T2, DQ, 0, ig_w2, DQ, 0, p_blend, DD, 0, ig_b2, 1.0f, p_h, x);

        // QKV = blended @ Wqkv^T + bqkv                  (2048 x 3072, K=1024)
        gemm_nt<128,128,16,8,8,EPI_NONE,false><<<dim3(24,16,1),256>>>(
            NTOK, 3*DD, DD, p_blend, DD, 0, p_wqkv, DD, 0, p_qkv, 3*DD, 0, p_bqkv, 1.0f, nullptr, nullptr);
        k_qkv_split<<<(unsigned)(((long long)NTOK*3*DD)/256),256>>>();

        // scores = (q @ k^T) * scale per (b,h)           (512 x 512, K=64) x 64
        gemm_nt<128,128,16,8,8,EPI_NONE,false><<<dim3(4,4,BHN),256>>>(
            SS, SS, DHD, p_q, DHD, (long long)SS*DHD, p_k, DHD, (long long)SS*DHD,
            p_sc, SS, (long long)SS*SS, nullptr, scale, nullptr, nullptr);

        k_softmax<<<BHN*SS,128>>>();

        // ctx = attn @ v  (via vT, NT form)              (512 x 64, K=512) x 64
        gemm_nt<64,64,16,4,4,EPI_NONE,false><<<dim3(1,8,BHN),256>>>(
            SS, DHD, SS, p_sc, SS, (long long)SS*SS, p_vT, SS, (long long)DHD*SS,
            p_ctx, DHD, (long long)SS*DHD, nullptr, 1.0f, nullptr, nullptr);
        k_ctx_r<<<(unsigned)(NHD/256),256>>>();

        // phi = ctx @ wo^T + bo                          (2048 x 1024, K=1024)
        gemm_nt<128,128,16,8,8,EPI_NONE,false><<<dim3(8,16,1),256>>>(
            NTOK, DD, DD, p_ctxr, DD, 0, wo, DD, 0, p_phi, DD, 0, bo, 1.0f, nullptr, nullptr);

        // h_new = LN(h + G1*phi), fused residual-norm reduction
        k_ln<<<NTOK,256>>>(lng, lnb);
        k_fin<<<1,1>>>(i);
        k_commit<<<(unsigned)(NHD/256),256>>>();
    }

    k_copy<<<(unsigned)((NHD+255)/256),256>>>(p_h, out, NHD);
    (void)in_sizes; (void)n_in; (void)out_size;
}

// round 2
// speedup vs baseline: 1.7925x; 1.7925x over previous
#include <cuda_runtime.h>
#include <cuda_bf16.h>
#include <math.h>
#include <stdint.h>

// ---------------- problem constants ----------------
#define BB 4
#define SS 512
#define DD 1024
#define HH 16
#define DHD 64
#define DQ 256
#define NTOK (BB*SS)            // 2048
#define BHN (BB*HH)             // 64
#define MIN_STEPS 4
#define MAX_STEPS 12

// ---------------- device state ----------------
__device__ int    g_act;
__device__ int    g_active;
__device__ int    g_num_steps;
__device__ float  g_gw0;
__device__ double g_red[2];

__device__ float g_h    [NTOK*DD];
__device__ float g_hnew [NTOK*DD];
__device__ float g_T1   [NTOK*DQ];
__device__ float g_G1   [NTOK*DD];
__device__ float g_T2   [NTOK*DQ];
__device__ float g_blend[NTOK*DD];
__device__ float g_wqkv [3*DD*DD];
__device__ float g_bqkv [3*DD];
__device__ float g_qkv  [NTOK*3*DD];
__device__ float g_q    [BHN*SS*DHD];
__device__ float g_k    [BHN*SS*DHD];
__device__ float g_vT   [BHN*DHD*SS];
__device__ float g_sc   [BHN*SS*SS];      // 64 MB scores scratch
__device__ float g_ctx  [BHN*SS*DHD];
__device__ float g_ctxr [NTOK*DD];
__device__ float g_phi  [NTOK*DD];
__device__ float g_pool [BB*DD];
__device__ float g_sph  [BB*DQ];

// ---------------- helpers ----------------
__device__ __forceinline__ float gelu_f(float v){ return 0.5f*v*(1.0f+erff(v*0.70710678118654752f)); }
__device__ __forceinline__ float sig_f (float v){ return 1.0f/(1.0f+__expf(-v)); }

template<typename T>
__device__ __forceinline__ T blockReduceSum(T v){
    static __shared__ T sh[32];
    int lane = threadIdx.x & 31, w = threadIdx.x >> 5;
    #pragma unroll
    for (int o = 16; o; o >>= 1) v += __shfl_down_sync(0xffffffffu, v, o);
    __syncthreads();
    if (lane == 0) sh[w] = v;
    __syncthreads();
    T r = (T)0;
    if (w == 0){
        int nw = (blockDim.x + 31) >> 5;
        r = (lane < nw) ? sh[lane] : (T)0;
        #pragma unroll
        for (int o = 16; o; o >>= 1) r += __shfl_down_sync(0xffffffffu, r, o);
    }
    return r;
}

__device__ __forceinline__ void mma16816(float* c, const uint32_t* a, const uint32_t* b){
    asm volatile(
        "mma.sync.aligned.m16n8k16.row.col.f32.bf16.bf16.f32 "
        "{%0,%1,%2,%3}, {%4,%5,%6,%7}, {%8,%9}, {%0,%1,%2,%3};\n"
        : "+f"(c[0]), "+f"(c[1]), "+f"(c[2]), "+f"(c[3])
        : "r"(a[0]), "r"(a[1]), "r"(a[2]), "r"(a[3]), "r"(b[0]), "r"(b[1]));
}

// ---------------- split-bf16 tensor-core NT GEMM with fused epilogues --------
// C[bz](m,n) = epi( alpha * sum_k A(m,k)*B(n,k) [+ C_old if ACC] [+ bias[n]] )
// Accuracy: A,B split into bf16 hi+lo; compute hi*hi + hi*lo + lo*hi (err ~2e-5).
enum { EPI_NONE=0, EPI_GELU=1, EPI_SIG=2, EPI_BLEND=3, EPI_GSCALE=4 };

template<int EPI, bool ACC>
__global__ void __launch_bounds__(256)
gemm_nt(int M,int N,int K,
        const float* __restrict__ A,int lda,long long sA,
        const float* __restrict__ B,int ldb,long long sB,
        float* __restrict__ C,int ldc,long long sC,
        const float* __restrict__ bias,float alpha,
        const float* __restrict__ Hp,const float* __restrict__ Xp)
{
    if (g_act == 0) return;
    constexpr int BM = 128, BN = 64, BK = 32, LDK = BK + 8;   // pad -> conflict-free LDS

    __shared__ __nv_bfloat16 Ah[BM*LDK];
    __shared__ __nv_bfloat16 Al[BM*LDK];
    __shared__ __nv_bfloat16 Bh[BN*LDK];
    __shared__ __nv_bfloat16 Bl[BN*LDK];

    const int tid  = threadIdx.x;
    const int lane = tid & 31;
    const int wid  = tid >> 5;
    const int wm   = wid >> 1;          // 0..3
    const int wn   = wid & 1;           // 0..1
    const int g    = lane >> 2;         // 0..7
    const int q    = lane & 3;          // 0..3

    const int bz = blockIdx.z;
    A += (long long)bz * sA;
    B += (long long)bz * sB;
    C += (long long)bz * sC;
    const int rm = blockIdx.y * BM;
    const int cn = blockIdx.x * BN;

    float acc[2][4][4];
    #pragma unroll
    for (int i=0;i<2;i++)
        #pragma unroll
        for (int j=0;j<4;j++)
            #pragma unroll
            for (int l=0;l<4;l++) acc[i][j][l] = 0.0f;

    for (int kt = 0; kt < K; kt += BK){
        // ---- stage A tile (128x32 fp32 -> bf16 hi/lo) : 1024 float4, 4 iters
        #pragma unroll
        for (int it=0; it<4; it++){
            int idx = tid + it*256;
            int row = idx >> 3;
            int c4  = (idx & 7) * 4;
            float4 v = *(const float4*)&A[(long long)(rm+row)*lda + kt + c4];
            float f0=v.x, f1=v.y, f2=v.z, f3=v.w;
            __nv_bfloat16 h0=__float2bfloat16(f0), h1=__float2bfloat16(f1),
                          h2=__float2bfloat16(f2), h3=__float2bfloat16(f3);
            __nv_bfloat16 l0=__float2bfloat16(f0-__bfloat162float(h0));
            __nv_bfloat16 l1=__float2bfloat16(f1-__bfloat162float(h1));
            __nv_bfloat16 l2=__float2bfloat16(f2-__bfloat162float(h2));
            __nv_bfloat16 l3=__float2bfloat16(f3-__bfloat162float(h3));
            int off = row*LDK + c4;
            __nv_bfloat162 p;
            p.x=h0; p.y=h1; *(__nv_bfloat162*)&Ah[off]   = p;
            p.x=h2; p.y=h3; *(__nv_bfloat162*)&Ah[off+2] = p;
            p.x=l0; p.y=l1; *(__nv_bfloat162*)&Al[off]   = p;
            p.x=l2; p.y=l3; *(__nv_bfloat162*)&Al[off+2] = p;
        }
        // ---- stage B tile (64x32) : 512 float4, 2 iters
        #pragma unroll
        for (int it=0; it<2; it++){
            int idx = tid + it*256;
            int row = idx >> 3;
            int c4  = (idx & 7) * 4;
            float4 v = *(const float4*)&B[(long long)(cn+row)*ldb + kt + c4];
            float f0=v.x, f1=v.y, f2=v.z, f3=v.w;
            __nv_bfloat16 h0=__float2bfloat16(f0), h1=__float2bfloat16(f1),
                          h2=__float2bfloat16(f2), h3=__float2bfloat16(f3);
            __nv_bfloat16 l0=__float2bfloat16(f0-__bfloat162float(h0));
            __nv_bfloat16 l1=__float2bfloat16(f1-__bfloat162float(h1));
            __nv_bfloat16 l2=__float2bfloat16(f2-__bfloat162float(h2));
            __nv_bfloat16 l3=__float2bfloat16(f3-__bfloat162float(h3));
            int off = row*LDK + c4;
            __nv_bfloat162 p;
            p.x=h0; p.y=h1; *(__nv_bfloat162*)&Bh[off]   = p;
            p.x=h2; p.y=h3; *(__nv_bfloat162*)&Bh[off+2] = p;
            p.x=l0; p.y=l1; *(__nv_bfloat162*)&Bl[off]   = p;
            p.x=l2; p.y=l3; *(__nv_bfloat162*)&Bl[off+2] = p;
        }
        __syncthreads();

        #pragma unroll
        for (int ks=0; ks<2; ks++){
            const int ko = ks*16;
            uint32_t aH[2][4], aL[2][4], bH[4][2], bL[4][2];
            #pragma unroll
            for (int ma=0; ma<2; ma++){
                int r = wm*32 + ma*16 + g;
                const __nv_bfloat16* ph = &Ah[r*LDK + ko + q*2];
                const __nv_bfloat16* pl = &Al[r*LDK + ko + q*2];
                aH[ma][0]=*(const uint32_t*)ph;
                aH[ma][1]=*(const uint32_t*)(ph + 8*LDK);
                aH[ma][2]=*(const uint32_t*)(ph + 8);
                aH[ma][3]=*(const uint32_t*)(ph + 8*LDK + 8);
                aL[ma][0]=*(const uint32_t*)pl;
                aL[ma][1]=*(const uint32_t*)(pl + 8*LDK);
                aL[ma][2]=*(const uint32_t*)(pl + 8);
                aL[ma][3]=*(const uint32_t*)(pl + 8*LDK + 8);
            }
            #pragma unroll
            for (int na=0; na<4; na++){
                int c = wn*32 + na*8 + g;
                const __nv_bfloat16* ph = &Bh[c*LDK + ko + q*2];
                const __nv_bfloat16* pl = &Bl[c*LDK + ko + q*2];
                bH[na][0]=*(const uint32_t*)ph; bH[na][1]=*(const uint32_t*)(ph+8);
                bL[na][0]=*(const uint32_t*)pl; bL[na][1]=*(const uint32_t*)(pl+8);
            }
            #pragma unroll
            for (int ma=0; ma<2; ma++)
                #pragma unroll
                for (int na=0; na<4; na++){
                    mma16816(acc[ma][na], aH[ma], bH[na]);
                    mma16816(acc[ma][na], aH[ma], bL[na]);
                    mma16816(acc[ma][na], aL[ma], bH[na]);
                }
        }
        __syncthreads();
    }

    // ---- epilogue
    #pragma unroll
    for (int ma=0; ma<2; ma++){
        int r0 = rm + wm*32 + ma*16 + g;
        #pragma unroll
        for (int na=0; na<4; na++){
            int c = cn + wn*32 + na*8 + q*2;
            #pragma unroll
            for (int hrow=0; hrow<2; hrow++){
                int r = r0 + hrow*8;
                long long gi = (long long)r*ldc + c;
                #pragma unroll
                for (int e=0; e<2; e++){
                    float v = acc[ma][na][hrow*2+e] * alpha;
                    if (ACC) v += C[gi+e];
                    if (bias) v += bias[c+e];
                    if      (EPI==EPI_GELU)   v = gelu_f(v);
                    else if (EPI==EPI_SIG)    v = sig_f(v);
                    else if (EPI==EPI_GSCALE) v = sig_f(v) * g_gw0;
                    else if (EPI==EPI_BLEND){
                        float s = sig_f(v);
                        v = s*Hp[gi+e] + (1.0f - s)*Xp[gi+e];
                    }
                    C[gi+e] = v;
                }
            }
        }
    }
}

// ---------------- small kernels ----------------
__global__ void k_copy(const float* __restrict__ s, float* __restrict__ d, long long n){
    long long i = (long long)blockIdx.x*blockDim.x + threadIdx.x;
    if (i < n) d[i] = s[i];
}

__global__ void k_pool(const float* __restrict__ h){
    int i = blockIdx.x*blockDim.x + threadIdx.x;
    if (i >= BB*DD) return;
    int b = i / DD, d = i % DD;
    const float* p = h + (long long)b*SS*DD + d;
    float s = 0.0f;
    for (int t=0;t<SS;t++) s += p[(long long)t*DD];
    g_pool[i] = s * (1.0f/(float)SS);
}

__global__ void k_sp1(const float* __restrict__ w1, const float* __restrict__ b1){
    int i = blockIdx.x*blockDim.x + threadIdx.x;
    if (i >= BB*DQ) return;
    int b = i / DQ, j = i % DQ;
    const float* p = g_pool + b*DD;
    const float* w = w1 + (long long)j*DD;
    float s = b1[j];
    for (int d=0; d<DD; d++) s = fmaf(p[d], w[d], s);
    g_sph[i] = gelu_f(s);
}

__global__ void k_init(const float* __restrict__ w2, const float* __restrict__ b2,
                       const float* __restrict__ gl){
    if (threadIdx.x != 0) return;
    float m = 0.0f;
    for (int b=0;b<BB;b++){
        float s = b2[0];
        for (int j=0;j<DQ;j++) s = fmaf(g_sph[b*DQ+j], w2[j], s);
        m += 1.0f/(1.0f + expf(-s));
    }
    m *= 1.0f/(float)BB;
    int ns = MIN_STEPS + (int)floorf(m * (float)(MAX_STEPS - MIN_STEPS));
    if (ns > MAX_STEPS) ns = MAX_STEPS;
    g_num_steps = ns;
    g_active = 1;
    float e0 = expf(gl[0]), e1 = expf(gl[1]), e2 = expf(gl[2]);
    g_gw0 = e0/(e0+e1+e2);
}

__global__ void k_begin(int i){
    if (threadIdx.x == 0){
        g_act = (g_active && (i < g_num_steps)) ? 1 : 0;
        g_red[0] = 0.0; g_red[1] = 0.0;
    }
}

__global__ void k_qkv_split(void){
    if (g_act == 0) return;
    long long i = (long long)blockIdx.x*blockDim.x + threadIdx.x;
    int t = (int)(i / (3*DD)), n = (int)(i % (3*DD));
    int which = n >> 10, w = n & 1023;
    int hh = w >> 6, dh = w & 63;
    int b = t >> 9, s = t & 511;
    int bh = b*HH + hh;
    float v = g_qkv[i];
    if      (which == 0) g_q [((long long)bh*SS + s)*DHD + dh] = v;
    else if (which == 1) g_k [((long long)bh*SS + s)*DHD + dh] = v;
    else                 g_vT[((long long)bh*DHD + dh)*SS + s] = v;
}

__global__ void k_softmax(void){
    if (g_act == 0) return;
    float* row = g_sc + (long long)blockIdx.x * SS;
    int t = threadIdx.x;
    float v0=row[t], v1=row[t+128], v2=row[t+256], v3=row[t+384];
    float mx = fmaxf(fmaxf(v0,v1), fmaxf(v2,v3));
    #pragma unroll
    for (int o=16;o;o>>=1) mx = fmaxf(mx, __shfl_xor_sync(0xffffffffu, mx, o));
    __shared__ float sm[4];
    if ((t&31)==0) sm[t>>5] = mx;
    __syncthreads();
    mx = fmaxf(fmaxf(sm[0],sm[1]), fmaxf(sm[2],sm[3]));
    v0 = __expf(v0-mx); v1 = __expf(v1-mx); v2 = __expf(v2-mx); v3 = __expf(v3-mx);
    float s = v0+v1+v2+v3;
    #pragma unroll
    for (int o=16;o;o>>=1) s += __shfl_xor_sync(0xffffffffu, s, o);
    __shared__ float sq[4];
    if ((t&31)==0) sq[t>>5] = s;
    __syncthreads();
    s = sq[0]+sq[1]+sq[2]+sq[3];
    float inv = 1.0f/s;
    row[t]=v0*inv; row[t+128]=v1*inv; row[t+256]=v2*inv; row[t+384]=v3*inv;
}

__global__ void k_ctx_r(void){
    if (g_act == 0) return;
    long long i = (long long)blockIdx.x*blockDim.x + threadIdx.x;
    int t = (int)(i / DD), d = (int)(i % DD);
    int b = t >> 9, s = t & 511;
    int hh = d >> 6, dh = d & 63;
    g_ctxr[i] = g_ctx[(((long long)(b*HH+hh))*SS + s)*DHD + dh];
}

__global__ void k_ln(const float* __restrict__ lg, const float* __restrict__ lb){
    if (g_act == 0) return;
    long long off = (long long)blockIdx.x * DD;
    int t = threadIdx.x;
    float u[4], hv[4];
    float sm = 0.0f;
    #pragma unroll
    for (int j=0;j<4;j++){
        int idx = t + j*256;
        hv[j] = g_h[off+idx];
        u[j]  = fmaf(g_G1[off+idx], g_phi[off+idx], hv[j]);
        sm += u[j];
    }
    sm = blockReduceSum<float>(sm);
    __shared__ float s_mean, s_inv;
    if (t==0) s_mean = sm * (1.0f/(float)DD);
    __syncthreads();
    float mean = s_mean, vs = 0.0f;
    #pragma unroll
    for (int j=0;j<4;j++){ float d = u[j]-mean; vs += d*d; }
    vs = blockReduceSum<float>(vs);
    if (t==0) s_inv = rsqrtf(vs*(1.0f/(float)DD) + 1e-5f);
    __syncthreads();
    float inv = s_inv;
    double dq = 0.0, hq = 0.0;
    #pragma unroll
    for (int j=0;j<4;j++){
        int idx = t + j*256;
        float y = (u[j]-mean)*inv*lg[idx] + lb[idx];
        g_hnew[off+idx] = y;
        float df = y - hv[j];
        dq += (double)df*(double)df;
        hq += (double)hv[j]*(double)hv[j];
    }
    dq = blockReduceSum<double>(dq);
    hq = blockReduceSum<double>(hq);
    if (t==0){ atomicAdd(&g_red[0], dq); atomicAdd(&g_red[1], hq); }
}

__global__ void k_fin(int i){
    if (threadIdx.x != 0) return;
    if (g_act == 0){ g_active = 0; return; }
    double res = sqrt(g_red[0]) / (sqrt(g_red[1]) + 1e-8);
    g_active = ((i >= MIN_STEPS) && (res < 1e-4)) ? 0 : 1;
}

__global__ void k_commit(void){
    if (g_act == 0) return;
    long long i = (long long)blockIdx.x*blockDim.x + threadIdx.x;
    g_h[i] = g_hnew[i];
}

// ---------------- host ----------------
static float* dptr(const void* symbol){
    void* p = nullptr;
    cudaGetSymbolAddress(&p, symbol);
    return (float*)p;
}

extern "C" void kernel_launch(void* const* d_in, const int* in_sizes, int n_in,
                              void* d_out, int out_size)
{
    const float* h     = (const float*)d_in[0];
    const float* x     = (const float*)d_in[1];
    const float* ig_w1 = (const float*)d_in[2];
    const float* ig_b1 = (const float*)d_in[3];
    const float* ig_w2 = (const float*)d_in[4];
    const float* ig_b2 = (const float*)d_in[5];
    const float* wq    = (const float*)d_in[6];
    const float* bq    = (const float*)d_in[7];
    const float* wk    = (const float*)d_in[8];
    const float* bk    = (const float*)d_in[9];
    const float* wv    = (const float*)d_in[10];
    const float* bv    = (const float*)d_in[11];
    const float* wo    = (const float*)d_in[12];
    const float* bo    = (const float*)d_in[13];
    const float* g1w1  = (const float*)d_in[14];
    const float* g1b1  = (const float*)d_in[15];
    const float* g1w2  = (const float*)d_in[16];
    const float* g1b2  = (const float*)d_in[17];
    const float* gl    = (const float*)d_in[18];
    const float* lng   = (const float*)d_in[19];
    const float* lnb   = (const float*)d_in[20];
    const float* spw1  = (const float*)d_in[21];
    const float* spb1  = (const float*)d_in[22];
    const float* spw2  = (const float*)d_in[23];
    const float* spb2  = (const float*)d_in[24];
    float* out = (float*)d_out;

    float* p_h     = dptr(g_h);
    float* p_T1    = dptr(g_T1);
    float* p_G1    = dptr(g_G1);
    float* p_T2    = dptr(g_T2);
    float* p_blend = dptr(g_blend);
    float* p_wqkv  = dptr(g_wqkv);
    float* p_bqkv  = dptr(g_bqkv);
    float* p_qkv   = dptr(g_qkv);
    float* p_q     = dptr(g_q);
    float* p_k     = dptr(g_k);
    float* p_vT    = dptr(g_vT);
    float* p_sc    = dptr(g_sc);
    float* p_ctx   = dptr(g_ctx);
    float* p_ctxr  = dptr(g_ctxr);
    float* p_phi   = dptr(g_phi);

    const long long NHD = (long long)NTOK*DD;
    const long long W1  = (long long)DD*DD;

    k_copy<<<(unsigned)((NHD+255)/256),256>>>(h,  p_h, NHD);
    k_copy<<<(unsigned)((W1+255)/256),256>>>(wq, p_wqkv,        W1);
    k_copy<<<(unsigned)((W1+255)/256),256>>>(wk, p_wqkv +   W1, W1);
    k_copy<<<(unsigned)((W1+255)/256),256>>>(wv, p_wqkv + 2*W1, W1);
    k_copy<<<4,256>>>(bq, p_bqkv,        DD);
    k_copy<<<4,256>>>(bk, p_bqkv +   DD, DD);
    k_copy<<<4,256>>>(bv, p_bqkv + 2*DD, DD);
    k_pool<<<(BB*DD+255)/256,256>>>(h);
    k_sp1 <<<(BB*DQ+255)/256,256>>>(spw1, spb1);
    k_init<<<1,32>>>(spw2, spb2, gl);

    const float scale = 0.125f;

    for (int i = 0; i < MAX_STEPS; i++){
        k_begin<<<1,32>>>(i);

        // T1 = gelu(h @ g1_w1^T + g1_b1)                  (2048 x 256, K=1024)
        gemm_nt<EPI_GELU,false><<<dim3(4,16,1),256>>>(
            NTOK, DQ, DD, p_h, DD, 0, g1w1, DD, 0, p_T1, DQ, 0, g1b1, 1.0f, nullptr, nullptr);

        // G1 = sigmoid(T1 @ g1_w2^T + g1_b2) * gw0        (2048 x 1024, K=256)
        gemm_nt<EPI_GSCALE,false><<<dim3(16,16,1),256>>>(
            NTOK, DD, DQ, p_T1, DQ, 0, g1w2, DQ, 0, p_G1, DD, 0, g1b2, 1.0f, nullptr, nullptr);

        // T2 = gelu(h @ ig_w1[:, :D]^T + x @ ig_w1[:, D:]^T + ig_b1)
        gemm_nt<EPI_NONE,false><<<dim3(4,16,1),256>>>(
            NTOK, DQ, DD, p_h, DD, 0, ig_w1, 2*DD, 0, p_T2, DQ, 0, nullptr, 1.0f, nullptr, nullptr);
        gemm_nt<EPI_GELU,true><<<dim3(4,16,1),256>>>(
            NTOK, DQ, DD, x, DD, 0, ig_w1 + DD, 2*DD, 0, p_T2, DQ, 0, ig_b1, 1.0f, nullptr, nullptr);

        // blended = sigmoid(T2 @ ig_w2^T + ig_b2)*h + (1-.)*x
        gemm_nt<EPI_BLEND,false><<<dim3(16,16,1),256>>>(
            NTOK, DD, DQ, p_T2, DQ, 0, ig_w2, DQ, 0, p_blend, DD, 0, ig_b2, 1.0f, p_h, x);

        // QKV = blended @ Wqkv^T + bqkv                   (2048 x 3072, K=1024)
        gemm_nt<EPI_NONE,false><<<dim3(48,16,1),256>>>(
            NTOK, 3*DD, DD, p_blend, DD, 0, p_wqkv, DD, 0, p_qkv, 3*DD, 0, p_bqkv, 1.0f, nullptr, nullptr);
        k_qkv_split<<<(unsigned)(((long long)NTOK*3*DD)/256),256>>>();

        // scores = (q @ k^T) * scale per (b,h)            (512 x 512, K=64) x 64
        gemm_nt<EPI_NONE,false><<<dim3(8,4,BHN),256>>>(
            SS, SS, DHD, p_q, DHD, (long long)SS*DHD, p_k, DHD, (long long)SS*DHD,
            p_sc, SS, (long long)SS*SS, nullptr, scale, nullptr, nullptr);

        k_softmax<<<BHN*SS,128>>>();

        // ctx = attn @ v (via vT)                         (512 x 64, K=512) x 64
        gemm_nt<EPI_NONE,false><<<dim3(1,4,BHN),256>>>(
            SS, DHD, SS, p_sc, SS, (long long)SS*SS, p_vT, SS, (long long)DHD*SS,
            p_ctx, DHD, (long long)SS*DHD, nullptr, 1.0f, nullptr, nullptr);
        k_ctx_r<<<(unsigned)(NHD/256),256>>>();

        // phi = ctx @ wo^T + bo                           (2048 x 1024, K=1024)
        gemm_nt<EPI_NONE,false><<<dim3(16,16,1),256>>>(
            NTOK, DD, DD, p_ctxr, DD, 0, wo, DD, 0, p_phi, DD, 0, bo, 1.0f, nullptr, nullptr);

        k_ln<<<NTOK,256>>>(lng, lnb);
        k_fin<<<1,1>>>(i);
        k_commit<<<(unsigned)(NHD/256),256>>>();
    }

    k_copy<<<(unsigned)((NHD+255)/256),256>>>(p_h, out, NHD);
    (void)in_sizes; (void)n_in; (void)out_size;
}

// round 3
// speedup vs baseline: 1.9166x; 1.0693x over previous
#include <cuda_runtime.h>
#include <cuda_bf16.h>
#include <math.h>
#include <stdint.h>

// ---------------- problem constants ----------------
#define BB 4
#define SS 512
#define DD 1024
#define HH 16
#define DHD 64
#define DQ 256
#define NTOK (BB*SS)            // 2048
#define BHN (BB*HH)             // 64
#define MIN_STEPS 4
#define MAX_STEPS 12

typedef __nv_bfloat16 bf16;

// ---------------- device state ----------------
__device__ int    g_act;
__device__ int    g_active;
__device__ int    g_num_steps;
__device__ float  g_gw0;
__device__ double g_red[2];

// fp32 buffers
__device__ float g_h   [NTOK*DD];
__device__ float g_G1  [NTOK*DD];
__device__ float g_phi [NTOK*DD];
__device__ float g_bqkv[3*DD];
__device__ float g_pool[BB*DD];
__device__ float g_sph [BB*DQ];

// split bf16 planes (hi / lo)
__device__ bf16 g_catH [NTOK*2*DD], g_catL [NTOK*2*DD];     // [h | x]
__device__ bf16 g_T1H  [NTOK*DQ],   g_T1L  [NTOK*DQ];
__device__ bf16 g_T2H  [NTOK*DQ],   g_T2L  [NTOK*DQ];
__device__ bf16 g_blnH [NTOK*DD],   g_blnL [NTOK*DD];
__device__ bf16 g_qkvH [NTOK*3*DD], g_qkvL [NTOK*3*DD];
__device__ bf16 g_ctxH [NTOK*DD],   g_ctxL [NTOK*DD];
// weight planes
__device__ bf16 g_w1H [DQ*DD],    g_w1L [DQ*DD];     // g1_w1
__device__ bf16 g_w2H [DD*DQ],    g_w2L [DD*DQ];     // g1_w2
__device__ bf16 g_iw1H[DQ*2*DD],  g_iw1L[DQ*2*DD];   // ig_w1 (256 x 2048)
__device__ bf16 g_iw2H[DD*DQ],    g_iw2L[DD*DQ];     // ig_w2
__device__ bf16 g_wqH [3*DD*DD],  g_wqL [3*DD*DD];   // wq|wk|wv
__device__ bf16 g_woH [DD*DD],    g_woL [DD*DD];     // wo

// ---------------- helpers ----------------
__device__ __forceinline__ float gelu_f(float v){ return 0.5f*v*(1.0f+erff(v*0.70710678118654752f)); }
__device__ __forceinline__ float sig_f (float v){ return 1.0f/(1.0f+__expf(-v)); }

__device__ __forceinline__ uint32_t pack_hi(float v0, float v1, float& r0, float& r1){
    bf16 h0 = __float2bfloat16(v0), h1 = __float2bfloat16(v1);
    r0 = v0 - __bfloat162float(h0);
    r1 = v1 - __bfloat162float(h1);
    return (uint32_t)__bfloat16_as_ushort(h0) | ((uint32_t)__bfloat16_as_ushort(h1) << 16);
}
__device__ __forceinline__ uint32_t pack_lo(float r0, float r1){
    return (uint32_t)__bfloat16_as_ushort(__float2bfloat16(r0)) |
           ((uint32_t)__bfloat16_as_ushort(__float2bfloat16(r1)) << 16);
}

template<typename T>
__device__ __forceinline__ T blockReduceSum(T v){
    static __shared__ T sh[32];
    int lane = threadIdx.x & 31, w = threadIdx.x >> 5;
    #pragma unroll
    for (int o = 16; o; o >>= 1) v += __shfl_down_sync(0xffffffffu, v, o);
    __syncthreads();
    if (lane == 0) sh[w] = v;
    __syncthreads();
    T r = (T)0;
    if (w == 0){
        int nw = (blockDim.x + 31) >> 5;
        r = (lane < nw) ? sh[lane] : (T)0;
        #pragma unroll
        for (int o = 16; o; o >>= 1) r += __shfl_down_sync(0xffffffffu, r, o);
    }
    return r;
}

__device__ __forceinline__ void mma16816(float* c, const uint32_t* a, const uint32_t* b){
    asm volatile(
        "mma.sync.aligned.m16n8k16.row.col.f32.bf16.bf16.f32 "
        "{%0,%1,%2,%3}, {%4,%5,%6,%7}, {%8,%9}, {%0,%1,%2,%3};\n"
        : "+f"(c[0]), "+f"(c[1]), "+f"(c[2]), "+f"(c[3])
        : "r"(a[0]), "r"(a[1]), "r"(a[2]), "r"(a[3]), "r"(b[0]), "r"(b[1]));
}

// ---------------- plane-input tensor-core NT GEMM -------------------------
// C(m,n) = epi( alpha * sum_k A(m,k)*B(n,k) + bias[n] ), A/B = bf16 hi+lo planes.
// 3-term split product: hi*hi + hi*lo + lo*hi.
enum { EPI_NONE=0, EPI_GELU=1, EPI_BLEND=3, EPI_GSCALE=4 };
// WM: 0 = write fp32 Cf, 1 = write split planes Ch/Cl

template<int EPI, int WM>
__global__ void __launch_bounds__(256)
gemm_pp(int M,int N,int K,
        const bf16* __restrict__ Ah, const bf16* __restrict__ Al, int lda,
        const bf16* __restrict__ Bh, const bf16* __restrict__ Bl, int ldb,
        float* __restrict__ Cf, bf16* __restrict__ Ch, bf16* __restrict__ Cl, int ldc,
        const float* __restrict__ bias, float alpha,
        const float* __restrict__ Hp, const float* __restrict__ Xp)
{
    if (g_act == 0) return;
    constexpr int BM = 128, BN = 64, BK = 32, LDK = BK + 8;

    __shared__ bf16 Ahs[BM*LDK];
    __shared__ bf16 Als[BM*LDK];
    __shared__ bf16 Bhs[BN*LDK];
    __shared__ bf16 Bls[BN*LDK];

    const int tid  = threadIdx.x;
    const int lane = tid & 31;
    const int wid  = tid >> 5;
    const int wm   = wid >> 1;
    const int wn   = wid & 1;
    const int g    = lane >> 2;
    const int q    = lane & 3;
    const int rm = blockIdx.y * BM;
    const int cn = blockIdx.x * BN;

    float acc[2][4][4];
    #pragma unroll
    for (int i=0;i<2;i++)
        #pragma unroll
        for (int j=0;j<4;j++)
            #pragma unroll
            for (int l=0;l<4;l++) acc[i][j][l] = 0.0f;

    for (int kt = 0; kt < K; kt += BK){
        #pragma unroll
        for (int it=0; it<2; it++){
            int idx = tid + it*256;
            int row = idx >> 2;
            int c8  = (idx & 3) * 8;
            long long go = (long long)(rm+row)*lda + kt + c8;
            *(uint4*)&Ahs[row*LDK + c8] = *(const uint4*)&Ah[go];
            *(uint4*)&Als[row*LDK + c8] = *(const uint4*)&Al[go];
        }
        {
            int row = tid >> 2;
            int c8  = (tid & 3) * 8;
            long long go = (long long)(cn+row)*ldb + kt + c8;
            *(uint4*)&Bhs[row*LDK + c8] = *(const uint4*)&Bh[go];
            *(uint4*)&Bls[row*LDK + c8] = *(const uint4*)&Bl[go];
        }
        __syncthreads();

        #pragma unroll
        for (int ks=0; ks<2; ks++){
            const int ko = ks*16;
            uint32_t aH[2][4], aL[2][4], bH[4][2], bL[4][2];
            #pragma unroll
            for (int ma=0; ma<2; ma++){
                int r = wm*32 + ma*16 + g;
                const bf16* ph = &Ahs[r*LDK + ko + q*2];
                const bf16* pl = &Als[r*LDK + ko + q*2];
                aH[ma][0]=*(const uint32_t*)ph;
                aH[ma][1]=*(const uint32_t*)(ph + 8*LDK);
                aH[ma][2]=*(const uint32_t*)(ph + 8);
                aH[ma][3]=*(const uint32_t*)(ph + 8*LDK + 8);
                aL[ma][0]=*(const uint32_t*)pl;
                aL[ma][1]=*(const uint32_t*)(pl + 8*LDK);
                aL[ma][2]=*(const uint32_t*)(pl + 8);
                aL[ma][3]=*(const uint32_t*)(pl + 8*LDK + 8);
            }
            #pragma unroll
            for (int na=0; na<4; na++){
                int c = wn*32 + na*8 + g;
                const bf16* ph = &Bhs[c*LDK + ko + q*2];
                const bf16* pl = &Bls[c*LDK + ko + q*2];
                bH[na][0]=*(const uint32_t*)ph; bH[na][1]=*(const uint32_t*)(ph+8);
                bL[na][0]=*(const uint32_t*)pl; bL[na][1]=*(const uint32_t*)(pl+8);
            }
            #pragma unroll
            for (int ma=0; ma<2; ma++)
                #pragma unroll
                for (int na=0; na<4; na++){
                    mma16816(acc[ma][na], aH[ma], bH[na]);
                    mma16816(acc[ma][na], aH[ma], bL[na]);
                    mma16816(acc[ma][na], aL[ma], bH[na]);
                }
        }
        __syncthreads();
    }

    // epilogue
    #pragma unroll
    for (int ma=0; ma<2; ma++){
        int r0 = rm + wm*32 + ma*16 + g;
        #pragma unroll
        for (int na=0; na<4; na++){
            int c = cn + wn*32 + na*8 + q*2;
            #pragma unroll
            for (int hrow=0; hrow<2; hrow++){
                int r = r0 + hrow*8;
                long long gi = (long long)r*ldc + c;
                float v[2];
                #pragma unroll
                for (int e=0; e<2; e++){
                    float t = acc[ma][na][hrow*2+e] * alpha;
                    if (bias) t += bias[c+e];
                    if      (EPI==EPI_GELU)   t = gelu_f(t);
                    else if (EPI==EPI_GSCALE) t = sig_f(t) * g_gw0;
                    else if (EPI==EPI_BLEND){
                        float s = sig_f(t);
                        t = s*Hp[gi+e] + (1.0f - s)*Xp[gi+e];
                    }
                    v[e] = t;
                }
                if (WM == 0){
                    Cf[gi] = v[0]; Cf[gi+1] = v[1];
                } else {
                    float r0f, r1f;
                    uint32_t ph = pack_hi(v[0], v[1], r0f, r1f);
                    uint32_t pl = pack_lo(r0f, r1f);
                    *(uint32_t*)&Ch[gi] = ph;
                    *(uint32_t*)&Cl[gi] = pl;
                }
            }
        }
    }
}

// ---------------- fused flash attention ----------------
// grid (4 qtiles, 64 bh), 256 threads. qkv planes in, ctx planes out.
#define LDQ 72
__global__ void __launch_bounds__(256) k_attn(void){
    if (g_act == 0) return;
    extern __shared__ char sm_[];
    bf16* Qh  = (bf16*)(sm_);
    bf16* Ql  = (bf16*)(sm_ + 18432);
    bf16* Kh  = (bf16*)(sm_ + 36864);
    bf16* Kl  = (bf16*)(sm_ + 36864 + 9216);
    bf16* Ph  = (bf16*)(sm_ + 36864);           // reuses K region
    bf16* Pl  = (bf16*)(sm_ + 36864 + 18432);
    bf16* Vth = (bf16*)(sm_ + 73728);
    bf16* Vtl = (bf16*)(sm_ + 82944);
    float* pm  = (float*)(sm_ + 92160);         // [2][128]
    float* ps  = pm + 256;                      // [2][128]
    float* m_s = ps + 256;                      // [128]
    float* l_s = m_s + 128;                     // [128]

    const int tid  = threadIdx.x;
    const int lane = tid & 31;
    const int wid  = tid >> 5;
    const int wm   = wid >> 1;
    const int wn   = wid & 1;
    const int g    = lane >> 2;
    const int q    = lane & 3;

    const int qt = blockIdx.x;
    const int bh = blockIdx.y;
    const int b  = bh >> 4, hh = bh & 15;
    const long long tb = (long long)b*SS + qt*128;
    const int qoff = hh*64;

    if (tid < 128){ m_s[tid] = -1e30f; l_s[tid] = 0.0f; }

    // stage Q (128 x 64) once
    #pragma unroll
    for (int it=0; it<4; it++){
        int idx = tid + it*256;
        int r = idx >> 3, c8 = (idx & 7)*8;
        long long go = (tb+r)*3072 + qoff + c8;
        *(uint4*)&Qh[r*LDQ + c8] = *(const uint4*)&g_qkvH[go];
        *(uint4*)&Ql[r*LDQ + c8] = *(const uint4*)&g_qkvL[go];
    }

    float acc_o[2][4][4];
    #pragma unroll
    for (int i=0;i<2;i++)
        #pragma unroll
        for (int j=0;j<4;j++)
            #pragma unroll
            for (int l=0;l<4;l++) acc_o[i][j][l]=0.0f;

    for (int kt = 0; kt < 8; kt++){
        __syncthreads();   // prev PV done; Q staged (first iter)
        const long long tk = (long long)b*SS + kt*64;
        #pragma unroll
        for (int it=0; it<2; it++){
            int idx = tid + it*256;
            int r = idx >> 3, c8 = (idx & 7)*8;
            long long go = (tk+r)*3072 + 1024 + qoff + c8;
            *(uint4*)&Kh[r*LDQ + c8] = *(const uint4*)&g_qkvH[go];
            *(uint4*)&Kl[r*LDQ + c8] = *(const uint4*)&g_qkvL[go];
        }
        #pragma unroll
        for (int it=0; it<8; it++){
            int idx = tid + it*256;
            int t = idx >> 5, d = (idx & 31)*2;
            long long go = (tk+t)*3072 + 2048 + qoff + d;
            uint32_t vh = *(const uint32_t*)&g_qkvH[go];
            uint32_t vl = *(const uint32_t*)&g_qkvL[go];
            *(uint16_t*)&Vth[ d   *LDQ + t] = (uint16_t)(vh & 0xffffu);
            *(uint16_t*)&Vth[(d+1)*LDQ + t] = (uint16_t)(vh >> 16);
            *(uint16_t*)&Vtl[ d   *LDQ + t] = (uint16_t)(vl & 0xffffu);
            *(uint16_t*)&Vtl[(d+1)*LDQ + t] = (uint16_t)(vl >> 16);
        }
        __syncthreads();

        // ---- S = Q @ K^T (warp: rows wm*32+0..31, cols wn*32+0..31)
        float acc_s[2][4][4];
        #pragma unroll
        for (int i=0;i<2;i++)
            #pragma unroll
            for (int j=0;j<4;j++)
                #pragma unroll
                for (int l=0;l<4;l++) acc_s[i][j][l]=0.0f;

        #pragma unroll
        for (int ko=0; ko<64; ko+=16){
            uint32_t aH[2][4], aL[2][4], bH[4][2], bL[4][2];
            #pragma unroll
            for (int ma=0; ma<2; ma++){
                int r = wm*32 + ma*16 + g;
                const bf16* ph = &Qh[r*LDQ + ko + q*2];
                const bf16* pl = &Ql[r*LDQ + ko + q*2];
                aH[ma][0]=*(const uint32_t*)ph;
                aH[ma][1]=*(const uint32_t*)(ph + 8*LDQ);
                aH[ma][2]=*(const uint32_t*)(ph + 8);
                aH[ma][3]=*(const uint32_t*)(ph + 8*LDQ + 8);
                aL[ma][0]=*(const uint32_t*)pl;
                aL[ma][1]=*(const uint32_t*)(pl + 8*LDQ);
                aL[ma][2]=*(const uint32_t*)(pl + 8);
                aL[ma][3]=*(const uint32_t*)(pl + 8*LDQ + 8);
            }
            #pragma unroll
            for (int na=0; na<4; na++){
                int c = wn*32 + na*8 + g;
                const bf16* ph = &Kh[c*LDQ + ko + q*2];
                const bf16* pl = &Kl[c*LDQ + ko + q*2];
                bH[na][0]=*(const uint32_t*)ph; bH[na][1]=*(const uint32_t*)(ph+8);
                bL[na][0]=*(const uint32_t*)pl; bL[na][1]=*(const uint32_t*)(pl+8);
            }
            #pragma unroll
            for (int ma=0; ma<2; ma++)
                #pragma unroll
                for (int na=0; na<4; na++){
                    mma16816(acc_s[ma][na], aH[ma], bH[na]);
                    mma16816(acc_s[ma][na], aH[ma], bL[na]);
                    mma16816(acc_s[ma][na], aL[ma], bH[na]);
                }
        }
        #pragma unroll
        for (int i=0;i<2;i++)
            #pragma unroll
            for (int j=0;j<4;j++)
                #pragma unroll
                for (int l=0;l<4;l++) acc_s[i][j][l] *= 0.125f;

        // ---- row max (per thread rows: wm*32+ma*16+rr*8+g)
        float rmx[2][2];
        #pragma unroll
        for (int ma=0; ma<2; ma++)
            #pragma unroll
            for (int rr=0; rr<2; rr++){
                float m = -1e30f;
                #pragma unroll
                for (int na=0; na<4; na++){
                    m = fmaxf(m, acc_s[ma][na][rr*2]);
                    m = fmaxf(m, acc_s[ma][na][rr*2+1]);
                }
                m = fmaxf(m, __shfl_xor_sync(0xffffffffu, m, 1));
                m = fmaxf(m, __shfl_xor_sync(0xffffffffu, m, 2));
                rmx[ma][rr] = m;
            }
        if (q == 0){
            #pragma unroll
            for (int ma=0; ma<2; ma++)
                #pragma unroll
                for (int rr=0; rr<2; rr++)
                    pm[wn*128 + wm*32 + ma*16 + rr*8 + g] = rmx[ma][rr];
        }
        __syncthreads();

        float mnew[2][2], sc[2][2];
        #pragma unroll
        for (int ma=0; ma<2; ma++)
            #pragma unroll
            for (int rr=0; rr<2; rr++){
                int r = wm*32 + ma*16 + rr*8 + g;
                float mo = m_s[r];
                float mn = fmaxf(mo, fmaxf(pm[r], pm[128+r]));
                mnew[ma][rr] = mn;
                sc[ma][rr] = __expf(mo - mn);
            }

        float rsm[2][2] = {{0,0},{0,0}};
        #pragma unroll
        for (int ma=0; ma<2; ma++)
            #pragma unroll
            for (int na=0; na<4; na++)
                #pragma unroll
                for (int e=0; e<4; e++){
                    int rr = e >> 1;
                    float p = __expf(acc_s[ma][na][e] - mnew[ma][rr]);
                    acc_s[ma][na][e] = p;
                    rsm[ma][rr] += p;
                }
        #pragma unroll
        for (int ma=0; ma<2; ma++)
            #pragma unroll
            for (int rr=0; rr<2; rr++){
                float s = rsm[ma][rr];
                s += __shfl_xor_sync(0xffffffffu, s, 1);
                s += __shfl_xor_sync(0xffffffffu, s, 2);
                rsm[ma][rr] = s;
            }
        if (q == 0){
            #pragma unroll
            for (int ma=0; ma<2; ma++)
                #pragma unroll
                for (int rr=0; rr<2; rr++)
                    ps[wn*128 + wm*32 + ma*16 + rr*8 + g] = rsm[ma][rr];
        }

        // write P split into smem (K region; S-MMA reads done per sync above)
        #pragma unroll
        for (int ma=0; ma<2; ma++){
            int r0 = wm*32 + ma*16 + g;
            #pragma unroll
            for (int na=0; na<4; na++){
                int c = wn*32 + na*8 + q*2;
                #pragma unroll
                for (int rr=0; rr<2; rr++){
                    int r = r0 + rr*8;
                    float l0, l1;
                    uint32_t phv = pack_hi(acc_s[ma][na][rr*2], acc_s[ma][na][rr*2+1], l0, l1);
                    uint32_t plv = pack_lo(l0, l1);
                    *(uint32_t*)&Ph[r*LDQ + c] = phv;
                    *(uint32_t*)&Pl[r*LDQ + c] = plv;
                }
            }
        }
        // rescale O
        #pragma unroll
        for (int ma=0; ma<2; ma++)
            #pragma unroll
            for (int na=0; na<4; na++)
                #pragma unroll
                for (int e=0; e<4; e++) acc_o[ma][na][e] *= sc[ma][e>>1];
        __syncthreads();

        if (wn == 0 && q == 0){
            #pragma unroll
            for (int ma=0; ma<2; ma++)
                #pragma unroll
                for (int rr=0; rr<2; rr++){
                    int r = wm*32 + ma*16 + rr*8 + g;
                    l_s[r] = l_s[r]*sc[ma][rr] + ps[r] + ps[128+r];
                    m_s[r] = mnew[ma][rr];
                }
        }

        // ---- O += P @ V (warp: rows wm*32.., dims wn*32..)
        #pragma unroll
        for (int ko=0; ko<64; ko+=16){
            uint32_t aH[2][4], aL[2][4], bH[4][2], bL[4][2];
            #pragma unroll
            for (int ma=0; ma<2; ma++){
                int r = wm*32 + ma*16 + g;
                const bf16* ph = &Ph[r*LDQ + ko + q*2];
                const bf16* pl = &Pl[r*LDQ + ko + q*2];
                aH[ma][0]=*(const uint32_t*)ph;
                aH[ma][1]=*(const uint32_t*)(ph + 8*LDQ);
                aH[ma][2]=*(const uint32_t*)(ph + 8);
                aH[ma][3]=*(const uint32_t*)(ph + 8*LDQ + 8);
                aL[ma][0]=*(const uint32_t*)pl;
                aL[ma][1]=*(const uint32_t*)(pl + 8*LDQ);
                aL[ma][2]=*(const uint32_t*)(pl + 8);
                aL[ma][3]=*(const uint32_t*)(pl + 8*LDQ + 8);
            }
            #pragma unroll
            for (int na=0; na<4; na++){
                int c = wn*32 + na*8 + g;
                const bf16* ph = &Vth[c*LDQ + ko + q*2];
                const bf16* pl = &Vtl[c*LDQ + ko + q*2];
                bH[na][0]=*(const uint32_t*)ph; bH[na][1]=*(const uint32_t*)(ph+8);
                bL[na][0]=*(const uint32_t*)pl; bL[na][1]=*(const uint32_t*)(pl+8);
            }
            #pragma unroll
            for (int ma=0; ma<2; ma++)
                #pragma unroll
                for (int na=0; na<4; na++){
                    mma16816(acc_o[ma][na], aH[ma], bH[na]);
                    mma16816(acc_o[ma][na], aH[ma], bL[na]);
                    mma16816(acc_o[ma][na], aL[ma], bH[na]);
                }
        }
    }
    __syncthreads();

    // epilogue: O /= l, write ctx planes at [token][h*64+d]
    #pragma unroll
    for (int ma=0; ma<2; ma++){
        int r0 = wm*32 + ma*16 + g;
        #pragma unroll
        for (int na=0; na<4; na++){
            int c = wn*32 + na*8 + q*2;
            #pragma unroll
            for (int rr=0; rr<2; rr++){
                int r = r0 + rr*8;
                float inv = 1.0f / l_s[r];
                float o0 = acc_o[ma][na][rr*2]   * inv;
                float o1 = acc_o[ma][na][rr*2+1] * inv;
                long long gi = (tb + r)*DD + qoff + c;
                float l0, l1;
                uint32_t phv = pack_hi(o0, o1, l0, l1);
                uint32_t plv = pack_lo(l0, l1);
                *(uint32_t*)&g_ctxH[gi] = phv;
                *(uint32_t*)&g_ctxL[gi] = plv;
            }
        }
    }
}

// ---------------- small kernels ----------------
__global__ void k_copy(const float* __restrict__ s, float* __restrict__ d, long long n){
    long long i = (long long)blockIdx.x*blockDim.x + threadIdx.x;
    if (i < n) d[i] = s[i];
}

__global__ void k_split(const float* __restrict__ s, bf16* __restrict__ dh,
                        bf16* __restrict__ dl, long long n){
    long long i = (long long)blockIdx.x*blockDim.x + threadIdx.x;
    if (i >= n) return;
    float v = s[i];
    bf16 h = __float2bfloat16(v);
    dh[i] = h;
    dl[i] = __float2bfloat16(v - __bfloat162float(h));
}

__global__ void k_split_cat(const float* __restrict__ s, int colOff){
    long long i = (long long)blockIdx.x*blockDim.x + threadIdx.x;   // [0, NTOK*DD)
    if (i >= (long long)NTOK*DD) return;
    int t = (int)(i >> 10), j = (int)(i & 1023);
    float v = s[i];
    bf16 h = __float2bfloat16(v);
    long long di = (long long)t*2*DD + colOff + j;
    g_catH[di] = h;
    g_catL[di] = __float2bfloat16(v - __bfloat162float(h));
}

__global__ void k_pool(const float* __restrict__ h){
    int i = blockIdx.x*blockDim.x + threadIdx.x;
    if (i >= BB*DD) return;
    int b = i / DD, d = i % DD;
    const float* p = h + (long long)b*SS*DD + d;
    float s = 0.0f;
    for (int t=0;t<SS;t++) s += p[(long long)t*DD];
    g_pool[i] = s * (1.0f/(float)SS);
}

__global__ void k_sp1(const float* __restrict__ w1, const float* __restrict__ b1){
    int i = blockIdx.x*blockDim.x + threadIdx.x;
    if (i >= BB*DQ) return;
    int b = i / DQ, j = i % DQ;
    const float* p = g_pool + b*DD;
    const float* w = w1 + (long long)j*DD;
    float s = b1[j];
    for (int d=0; d<DD; d++) s = fmaf(p[d], w[d], s);
    g_sph[i] = gelu_f(s);
}

__global__ void k_init(const float* __restrict__ w2, const float* __restrict__ b2,
                       const float* __restrict__ gl){
    if (threadIdx.x != 0) return;
    float m = 0.0f;
    for (int b=0;b<BB;b++){
        float s = b2[0];
        for (int j=0;j<DQ;j++) s = fmaf(g_sph[b*DQ+j], w2[j], s);
        m += 1.0f/(1.0f + expf(-s));
    }
    m *= 1.0f/(float)BB;
    int ns = MIN_STEPS + (int)floorf(m * (float)(MAX_STEPS - MIN_STEPS));
    if (ns > MAX_STEPS) ns = MAX_STEPS;
    g_num_steps = ns;
    g_active = 1;
    float e0 = expf(gl[0]), e1 = expf(gl[1]), e2 = expf(gl[2]);
    g_gw0 = e0/(e0+e1+e2);
}

__global__ void k_begin(int i){
    if (threadIdx.x == 0){
        g_act = (g_active && (i < g_num_steps)) ? 1 : 0;
        g_red[0] = 0.0; g_red[1] = 0.0;
    }
}

__global__ void k_ln(const float* __restrict__ lg, const float* __restrict__ lb){
    if (g_act == 0) return;
    long long off = (long long)blockIdx.x * DD;
    int t = threadIdx.x;
    float u[4], hv[4];
    float sm = 0.0f;
    #pragma unroll
    for (int j=0;j<4;j++){
        int idx = t + j*256;
        hv[j] = g_h[off+idx];
        u[j]  = fmaf(g_G1[off+idx], g_phi[off+idx], hv[j]);
        sm += u[j];
    }
    sm = blockReduceSum<float>(sm);
    __shared__ float s_mean, s_inv;
    if (t==0) s_mean = sm * (1.0f/(float)DD);
    __syncthreads();
    float mean = s_mean, vs = 0.0f;
    #pragma unroll
    for (int j=0;j<4;j++){ float d = u[j]-mean; vs += d*d; }
    vs = blockReduceSum<float>(vs);
    if (t==0) s_inv = rsqrtf(vs*(1.0f/(float)DD) + 1e-5f);
    __syncthreads();
    float inv = s_inv;
    double dq = 0.0, hq = 0.0;
    long long cbase = (long long)blockIdx.x * 2*DD;
    #pragma unroll
    for (int j=0;j<4;j++){
        int idx = t + j*256;
        float y = (u[j]-mean)*inv*lg[idx] + lb[idx];
        g_h[off+idx] = y;                       // in-place commit
        bf16 hb = __float2bfloat16(y);
        g_catH[cbase+idx] = hb;
        g_catL[cbase+idx] = __float2bfloat16(y - __bfloat162float(hb));
        float df = y - hv[j];
        dq += (double)df*(double)df;
        hq += (double)hv[j]*(double)hv[j];
    }
    dq = blockReduceSum<double>(dq);
    hq = blockReduceSum<double>(hq);
    if (t==0){ atomicAdd(&g_red[0], dq); atomicAdd(&g_red[1], hq); }
}

__global__ void k_fin(int i){
    if (threadIdx.x != 0) return;
    if (g_act == 0){ g_active = 0; return; }
    double res = sqrt(g_red[0]) / (sqrt(g_red[1]) + 1e-8);
    g_active = ((i >= MIN_STEPS) && (res < 1e-4)) ? 0 : 1;
}

// ---------------- host ----------------
template<typename T>
static T* dptr(const void* symbol){
    void* p = nullptr;
    cudaGetSymbolAddress(&p, symbol);
    return (T*)p;
}

extern "C" void kernel_launch(void* const* d_in, const int* in_sizes, int n_in,
                              void* d_out, int out_size)
{
    const float* h     = (const float*)d_in[0];
    const float* x     = (const float*)d_in[1];
    const float* ig_w1 = (const float*)d_in[2];
    const float* ig_b1 = (const float*)d_in[3];
    const float* ig_w2 = (const float*)d_in[4];
    const float* ig_b2 = (const float*)d_in[5];
    const float* wq    = (const float*)d_in[6];
    const float* bq    = (const float*)d_in[7];
    const float* wk    = (const float*)d_in[8];
    const float* bk    = (const float*)d_in[9];
    const float* wv    = (const float*)d_in[10];
    const float* bv    = (const float*)d_in[11];
    const float* wo    = (const float*)d_in[12];
    const float* bo    = (const float*)d_in[13];
    const float* g1w1  = (const float*)d_in[14];
    const float* g1b1  = (const float*)d_in[15];
    const float* g1w2  = (const float*)d_in[16];
    const float* g1b2  = (const float*)d_in[17];
    const float* gl    = (const float*)d_in[18];
    const float* lng   = (const float*)d_in[19];
    const float* lnb   = (const float*)d_in[20];
    const float* spw1  = (const float*)d_in[21];
    const float* spb1  = (const float*)d_in[22];
    const float* spw2  = (const float*)d_in[23];
    const float* spb2  = (const float*)d_in[24];
    float* out = (float*)d_out;

    float* p_h    = dptr<float>(g_h);
    float* p_G1   = dptr<float>(g_G1);
    float* p_phi  = dptr<float>(g_phi);
    float* p_bqkv = dptr<float>(g_bqkv);
    bf16 *p_catH = dptr<bf16>(g_catH), *p_catL = dptr<bf16>(g_catL);
    bf16 *p_T1H  = dptr<bf16>(g_T1H),  *p_T1L  = dptr<bf16>(g_T1L);
    bf16 *p_T2H  = dptr<bf16>(g_T2H),  *p_T2L  = dptr<bf16>(g_T2L);
    bf16 *p_blnH = dptr<bf16>(g_blnH), *p_blnL = dptr<bf16>(g_blnL);
    bf16 *p_qkvH = dptr<bf16>(g_qkvH), *p_qkvL = dptr<bf16>(g_qkvL);
    bf16 *p_ctxH = dptr<bf16>(g_ctxH), *p_ctxL = dptr<bf16>(g_ctxL);
    bf16 *p_w1H  = dptr<bf16>(g_w1H),  *p_w1L  = dptr<bf16>(g_w1L);
    bf16 *p_w2H  = dptr<bf16>(g_w2H),  *p_w2L  = dptr<bf16>(g_w2L);
    bf16 *p_iw1H = dptr<bf16>(g_iw1H), *p_iw1L = dptr<bf16>(g_iw1L);
    bf16 *p_iw2H = dptr<bf16>(g_iw2H), *p_iw2L = dptr<bf16>(g_iw2L);
    bf16 *p_wqH  = dptr<bf16>(g_wqH),  *p_wqL  = dptr<bf16>(g_wqL);
    bf16 *p_woH  = dptr<bf16>(g_woH),  *p_woL  = dptr<bf16>(g_woL);

    const long long NHD = (long long)NTOK*DD;
    const long long W1  = (long long)DD*DD;

    cudaFuncSetAttribute(k_attn, cudaFuncAttributeMaxDynamicSharedMemorySize, 96*1024);

    // ---- setup: fp32 copies + split planes
    k_copy<<<(unsigned)((NHD+255)/256),256>>>(h, p_h, NHD);
    k_split_cat<<<(unsigned)((NHD+255)/256),256>>>(h, 0);
    k_split_cat<<<(unsigned)((NHD+255)/256),256>>>(x, DD);
    k_split<<<(DQ*DD+255)/256,256>>>(g1w1,  p_w1H,  p_w1L,  DQ*DD);
    k_split<<<(DD*DQ+255)/256,256>>>(g1w2,  p_w2H,  p_w2L,  DD*DQ);
    k_split<<<(DQ*2*DD+255)/256,256>>>(ig_w1, p_iw1H, p_iw1L, DQ*2*DD);
    k_split<<<(DD*DQ+255)/256,256>>>(ig_w2, p_iw2H, p_iw2L, DD*DQ);
    k_split<<<(unsigned)((W1+255)/256),256>>>(wq, p_wqH,        p_wqL,        W1);
    k_split<<<(unsigned)((W1+255)/256),256>>>(wk, p_wqH + W1,   p_wqL + W1,   W1);
    k_split<<<(unsigned)((W1+255)/256),256>>>(wv, p_wqH + 2*W1, p_wqL + 2*W1, W1);
    k_split<<<(unsigned)((W1+255)/256),256>>>(wo, p_woH, p_woL, W1);
    k_copy<<<4,256>>>(bq, p_bqkv,        DD);
    k_copy<<<4,256>>>(bk, p_bqkv +   DD, DD);
    k_copy<<<4,256>>>(bv, p_bqkv + 2*DD, DD);
    k_pool<<<(BB*DD+255)/256,256>>>(h);
    k_sp1 <<<(BB*DQ+255)/256,256>>>(spw1, spb1);
    k_init<<<1,32>>>(spw2, spb2, gl);

    for (int i = 0; i < MAX_STEPS; i++){
        k_begin<<<1,32>>>(i);

        // T1 = gelu(h @ g1_w1^T + g1_b1)            M2048 N256 K1024
        gemm_pp<EPI_GELU,1><<<dim3(4,16),256>>>(
            NTOK, DQ, DD, p_catH, p_catL, 2*DD, p_w1H, p_w1L, DD,
            nullptr, p_T1H, p_T1L, DQ, g1b1, 1.0f, nullptr, nullptr);

        // G1 = sigmoid(T1 @ g1_w2^T + g1_b2)*gw0    M2048 N1024 K256
        gemm_pp<EPI_GSCALE,0><<<dim3(16,16),256>>>(
            NTOK, DD, DQ, p_T1H, p_T1L, DQ, p_w2H, p_w2L, DQ,
            p_G1, nullptr, nullptr, DD, g1b2, 1.0f, nullptr, nullptr);

        // T2 = gelu([h|x] @ ig_w1^T + ig_b1)        M2048 N256 K2048
        gemm_pp<EPI_GELU,1><<<dim3(4,16),256>>>(
            NTOK, DQ, 2*DD, p_catH, p_catL, 2*DD, p_iw1H, p_iw1L, 2*DD,
            nullptr, p_T2H, p_T2L, DQ, ig_b1, 1.0f, nullptr, nullptr);

        // blended = sig(T2 @ ig_w2^T + b)*h+(1-s)*x M2048 N1024 K256
        gemm_pp<EPI_BLEND,1><<<dim3(16,16),256>>>(
            NTOK, DD, DQ, p_T2H, p_T2L, DQ, p_iw2H, p_iw2L, DQ,
            nullptr, p_blnH, p_blnL, DD, ig_b2, 1.0f, p_h, x);

        // QKV = blended @ Wqkv^T + bqkv             M2048 N3072 K1024
        gemm_pp<EPI_NONE,1><<<dim3(48,16),256>>>(
            NTOK, 3*DD, DD, p_blnH, p_blnL, DD, p_wqH, p_wqL, DD,
            nullptr, p_qkvH, p_qkvL, 3*DD, p_bqkv, 1.0f, nullptr, nullptr);

        // fused flash attention -> ctx planes
        k_attn<<<dim3(4,BHN),256,96*1024>>>();

        // phi = ctx @ wo^T + bo                     M2048 N1024 K1024
        gemm_pp<EPI_NONE,0><<<dim3(16,16),256>>>(
            NTOK, DD, DD, p_ctxH, p_ctxL, DD, p_woH, p_woL, DD,
            p_phi, nullptr, nullptr, DD, bo, 1.0f, nullptr, nullptr);

        // h = LN(h + G1*phi) in place + residual reduction + cat planes
        k_ln<<<NTOK,256>>>(lng, lnb);
        k_fin<<<1,1>>>(i);
    }

    k_copy<<<(unsigned)((NHD+255)/256),256>>>(p_h, out, NHD);
    (void)in_sizes; (void)n_in; (void)out_size;
}

// round 5
// speedup vs baseline: 2.3677x; 1.2354x over previous
#include <cuda_runtime.h>
#include <cuda_bf16.h>
#include <math.h>
#include <stdint.h>

// ---------------- problem constants ----------------
#define BB 4
#define SS 512
#define DD 1024
#define HH 16
#define DHD 64
#define DQ 256
#define NTOK (BB*SS)            // 2048
#define BHN (BB*HH)             // 64
#define MIN_STEPS 4
#define MAX_STEPS 12

typedef __nv_bfloat16 bf16;

// ---------------- device state ----------------
__device__ int    g_act;
__device__ int    g_active;
__device__ int    g_num_steps;
__device__ float  g_gw0;
__device__ double g_red[2];

// fp32 buffers
__device__ float g_h   [NTOK*DD];
__device__ float g_G1  [NTOK*DD];
__device__ float g_phi [NTOK*DD];
__device__ float g_bqkv[3*DD];
__device__ float g_pool[BB*DD];
__device__ float g_sph [BB*DQ];

// split bf16 planes (hi / lo)
__device__ bf16 g_catH [NTOK*2*DD], g_catL [NTOK*2*DD];     // [h | x]
__device__ bf16 g_T1H  [NTOK*DQ],   g_T1L  [NTOK*DQ];
__device__ bf16 g_T2H  [NTOK*DQ],   g_T2L  [NTOK*DQ];
__device__ bf16 g_blnH [NTOK*DD],   g_blnL [NTOK*DD];
__device__ bf16 g_qkvH [NTOK*3*DD], g_qkvL [NTOK*3*DD];
__device__ bf16 g_ctxH [NTOK*DD],   g_ctxL [NTOK*DD];
// weight planes
__device__ bf16 g_w1H [DQ*DD],    g_w1L [DQ*DD];
__device__ bf16 g_w2H [DD*DQ],    g_w2L [DD*DQ];
__device__ bf16 g_iw1H[DQ*2*DD],  g_iw1L[DQ*2*DD];
__device__ bf16 g_iw2H[DD*DQ],    g_iw2L[DD*DQ];
__device__ bf16 g_wqH [3*DD*DD],  g_wqL [3*DD*DD];
__device__ bf16 g_woH [DD*DD],    g_woL [DD*DD];

// ---------------- scalar helpers ----------------
__device__ __forceinline__ float gelu_f(float v){ return 0.5f*v*(1.0f+erff(v*0.70710678118654752f)); }
__device__ __forceinline__ float sig_f (float v){ return 1.0f/(1.0f+__expf(-v)); }

__device__ __forceinline__ uint32_t pack_hi(float v0, float v1, float& r0, float& r1){
    bf16 h0 = __float2bfloat16(v0), h1 = __float2bfloat16(v1);
    r0 = v0 - __bfloat162float(h0);
    r1 = v1 - __bfloat162float(h1);
    return (uint32_t)__bfloat16_as_ushort(h0) | ((uint32_t)__bfloat16_as_ushort(h1) << 16);
}
__device__ __forceinline__ uint32_t pack_lo(float r0, float r1){
    return (uint32_t)__bfloat16_as_ushort(__float2bfloat16(r0)) |
           ((uint32_t)__bfloat16_as_ushort(__float2bfloat16(r1)) << 16);
}

template<typename T>
__device__ __forceinline__ T blockReduceSum(T v){
    static __shared__ T sh[32];
    int lane = threadIdx.x & 31, w = threadIdx.x >> 5;
    #pragma unroll
    for (int o = 16; o; o >>= 1) v += __shfl_down_sync(0xffffffffu, v, o);
    __syncthreads();
    if (lane == 0) sh[w] = v;
    __syncthreads();
    T r = (T)0;
    if (w == 0){
        int nw = (blockDim.x + 31) >> 5;
        r = (lane < nw) ? sh[lane] : (T)0;
        #pragma unroll
        for (int o = 16; o; o >>= 1) r += __shfl_down_sync(0xffffffffu, r, o);
    }
    return r;
}

__device__ __forceinline__ uint32_t s2u(const void* p){
    uint32_t a;
    asm("{ .reg .u64 t; cvta.to.shared.u64 t, %1; cvt.u32.u64 %0, t; }" : "=r"(a) : "l"(p));
    return a;
}
#define CPA16(d,s) asm volatile("cp.async.cg.shared.global [%0], [%1], 16;\n" :: "r"(d), "l"(s))
#define CPCOMMIT() asm volatile("cp.async.commit_group;\n" ::: "memory")
__device__ __forceinline__ void cpwait1(){ asm volatile("cp.async.wait_group 1;\n" ::: "memory"); }
__device__ __forceinline__ void cpwait0(){ asm volatile("cp.async.wait_group 0;\n" ::: "memory"); }

__device__ __forceinline__ void mma16816(float* c, const uint32_t* a, const uint32_t* b){
    asm volatile(
        "mma.sync.aligned.m16n8k16.row.col.f32.bf16.bf16.f32 "
        "{%0,%1,%2,%3}, {%4,%5,%6,%7}, {%8,%9}, {%0,%1,%2,%3};\n"
        : "+f"(c[0]), "+f"(c[1]), "+f"(c[2]), "+f"(c[3])
        : "r"(a[0]), "r"(a[1]), "r"(a[2]), "r"(a[3]), "r"(b[0]), "r"(b[1]));
}

// ---------------- pipelined split-bf16 HMMA NT GEMM core -------------------
// C(m,n) = epi( sum_k A(m,k)*B(n,k) + bias[n] ), A/B bf16 hi+lo planes,
// 3-term split (hi*hi + hi*lo + lo*hi). cp.async 2-stage double buffer.
enum { EPI_NONE=0, EPI_GELU=1, EPI_BLEND=3, EPI_GSCALE=4 };

struct GemmJob {
    int K;
    const bf16 *Ah, *Al; int lda;
    const bf16 *Bh, *Bl; int ldb;
    float* Cf; bf16 *Ch, *Cl; int ldc;
    const float* bias;
};

#define GBM 128
#define GBN 64
#define GBK 32
#define GLDK 40
// per-stage byte layout: Ah(10240) Al(10240) Bh(5120) Bl(5120) = 30720
#define STG_BYTES 30720
#define OFF_AL 10240u
#define OFF_BH 20480u
#define OFF_BL 25600u

template<int EPI,int WM>
__device__ __forceinline__ void gemm_core(const GemmJob J, char* buf,
                                          const float* Hp, const float* Xp)
{
    const int tid  = threadIdx.x;
    const int lane = tid & 31;
    const int wid  = tid >> 5;
    const int wm   = wid >> 1;
    const int wn   = wid & 1;
    const int g    = lane >> 2;
    const int q    = lane & 3;
    const int rm = blockIdx.y * GBM;
    const int cn = blockIdx.x * GBN;
    const uint32_t sb = s2u(buf);

    auto stg = [&](int st, int kt){
        uint32_t sa = sb + (uint32_t)st * STG_BYTES;
        #pragma unroll
        for (int it=0; it<2; it++){
            int idx = tid + it*256;
            int row = idx >> 2;
            int c8  = (idx & 3) * 8;
            size_t go = (size_t)(rm+row)*J.lda + kt + c8;
            uint32_t d = sa + (uint32_t)(row*GLDK + c8)*2;
            CPA16(d,          J.Ah + go);
            CPA16(d + OFF_AL, J.Al + go);
        }
        {
            int row = tid >> 2;
            int c8  = (tid & 3) * 8;
            size_t go = (size_t)(cn+row)*J.ldb + kt + c8;
            uint32_t d = sa + OFF_BH + (uint32_t)(row*GLDK + c8)*2;
            CPA16(d,                    J.Bh + go);
            CPA16(d + (OFF_BL-OFF_BH),  J.Bl + go);
        }
        CPCOMMIT();
    };

    float acc[2][4][4];
    #pragma unroll
    for (int i=0;i<2;i++)
        #pragma unroll
        for (int j=0;j<4;j++)
            #pragma unroll
            for (int l=0;l<4;l++) acc[i][j][l] = 0.0f;

    const int niter = J.K / GBK;
    stg(0, 0);
    stg(1, GBK);

    for (int i=0; i<niter; i++){
        const int st = i & 1;
        bf16* Ahs = (bf16*)(buf + st*STG_BYTES);
        bf16* Als = (bf16*)(buf + st*STG_BYTES + OFF_AL);
        bf16* Bhs = (bf16*)(buf + st*STG_BYTES + OFF_BH);
        bf16* Bls = (bf16*)(buf + st*STG_BYTES + OFF_BL);

        if (i+1 < niter) cpwait1(); else cpwait0();
        __syncthreads();

        #pragma unroll
        for (int ks=0; ks<2; ks++){
            const int ko = ks*16;
            uint32_t aH[2][4], aL[2][4], bH[4][2], bL[4][2];
            #pragma unroll
            for (int ma=0; ma<2; ma++){
                int r = wm*32 + ma*16 + g;
                const bf16* ph = &Ahs[r*GLDK + ko + q*2];
                const bf16* pl = &Als[r*GLDK + ko + q*2];
                aH[ma][0]=*(const uint32_t*)ph;
                aH[ma][1]=*(const uint32_t*)(ph + 8*GLDK);
                aH[ma][2]=*(const uint32_t*)(ph + 8);
                aH[ma][3]=*(const uint32_t*)(ph + 8*GLDK + 8);
                aL[ma][0]=*(const uint32_t*)pl;
                aL[ma][1]=*(const uint32_t*)(pl + 8*GLDK);
                aL[ma][2]=*(const uint32_t*)(pl + 8);
                aL[ma][3]=*(const uint32_t*)(pl + 8*GLDK + 8);
            }
            #pragma unroll
            for (int na=0; na<4; na++){
                int c = wn*32 + na*8 + g;
                const bf16* ph = &Bhs[c*GLDK + ko + q*2];
                const bf16* pl = &Bls[c*GLDK + ko + q*2];
                bH[na][0]=*(const uint32_t*)ph; bH[na][1]=*(const uint32_t*)(ph+8);
                bL[na][0]=*(const uint32_t*)pl; bL[na][1]=*(const uint32_t*)(pl+8);
            }
            #pragma unroll
            for (int ma=0; ma<2; ma++)
                #pragma unroll
                for (int na=0; na<4; na++){
                    mma16816(acc[ma][na], aH[ma], bH[na]);
                    mma16816(acc[ma][na], aH[ma], bL[na]);
                    mma16816(acc[ma][na], aL[ma], bH[na]);
                }
        }
        __syncthreads();
        if (i+2 < niter) stg(st, (i+2)*GBK);
    }

    // epilogue
    #pragma unroll
    for (int ma=0; ma<2; ma++){
        int r0 = rm + wm*32 + ma*16 + g;
        #pragma unroll
        for (int na=0; na<4; na++){
            int c = cn + wn*32 + na*8 + q*2;
            #pragma unroll
            for (int hrow=0; hrow<2; hrow++){
                int r = r0 + hrow*8;
                long long gi = (long long)r*J.ldc + c;
                float v[2];
                #pragma unroll
                for (int e=0; e<2; e++){
                    float t = acc[ma][na][hrow*2+e];
                    if (J.bias) t += J.bias[c+e];
                    if      (EPI==EPI_GELU)   t = gelu_f(t);
                    else if (EPI==EPI_GSCALE) t = sig_f(t) * g_gw0;
                    else if (EPI==EPI_BLEND){
                        float s = sig_f(t);
                        t = s*Hp[gi+e] + (1.0f - s)*Xp[gi+e];
                    }
                    v[e] = t;
                }
                if (WM == 0){
                    J.Cf[gi] = v[0]; J.Cf[gi+1] = v[1];
                } else {
                    float r0f, r1f;
                    uint32_t ph = pack_hi(v[0], v[1], r0f, r1f);
                    uint32_t pl = pack_lo(r0f, r1f);
                    *(uint32_t*)&J.Ch[gi] = ph;
                    *(uint32_t*)&J.Cl[gi] = pl;
                }
            }
        }
    }
}

template<int EPI,int WM>
__global__ void __launch_bounds__(256)
gemm_one(GemmJob J, const float* Hp, const float* Xp){
    if (g_act == 0) return;
    __shared__ char buf[2*STG_BYTES];
    gemm_core<EPI,WM>(J, buf, Hp, Xp);
}

template<int E0,int W0,int E1,int W1>
__global__ void __launch_bounds__(256)
gemm_dual(GemmJob J0, GemmJob J1, const float* Hp, const float* Xp){
    if (g_act == 0) return;
    __shared__ char buf[2*STG_BYTES];
    if (blockIdx.z == 0) gemm_core<E0,W0>(J0, buf, Hp, Xp);
    else                 gemm_core<E1,W1>(J1, buf, Hp, Xp);
}

// ---------------- fused flash attention ----------------
#define LDQ 72
__global__ void __launch_bounds__(256) k_attn(void){
    if (g_act == 0) return;
    extern __shared__ char sm_[];
    bf16* Qh  = (bf16*)(sm_);
    bf16* Ql  = (bf16*)(sm_ + 18432);
    bf16* Kh  = (bf16*)(sm_ + 36864);
    bf16* Kl  = (bf16*)(sm_ + 36864 + 9216);
    bf16* Ph  = (bf16*)(sm_ + 36864);
    bf16* Pl  = (bf16*)(sm_ + 36864 + 18432);
    bf16* Vth = (bf16*)(sm_ + 73728);
    bf16* Vtl = (bf16*)(sm_ + 82944);
    float* pm  = (float*)(sm_ + 92160);
    float* ps  = pm + 256;
    float* m_s = ps + 256;
    float* l_s = m_s + 128;

    const int tid  = threadIdx.x;
    const int lane = tid & 31;
    const int wid  = tid >> 5;
    const int wm   = wid >> 1;
    const int wn   = wid & 1;
    const int g    = lane >> 2;
    const int q    = lane & 3;

    const int qt = blockIdx.x;
    const int bh = blockIdx.y;
    const int b  = bh >> 4, hh = bh & 15;
    const long long tb = (long long)b*SS + qt*128;
    const int qoff = hh*64;

    if (tid < 128){ m_s[tid] = -1e30f; l_s[tid] = 0.0f; }

    #pragma unroll
    for (int it=0; it<4; it++){
        int idx = tid + it*256;
        int r = idx >> 3, c8 = (idx & 7)*8;
        long long go = (tb+r)*3072 + qoff + c8;
        *(uint4*)&Qh[r*LDQ + c8] = *(const uint4*)&g_qkvH[go];
        *(uint4*)&Ql[r*LDQ + c8] = *(const uint4*)&g_qkvL[go];
    }

    float acc_o[2][4][4];
    #pragma unroll
    for (int i=0;i<2;i++)
        #pragma unroll
        for (int j=0;j<4;j++)
            #pragma unroll
            for (int l=0;l<4;l++) acc_o[i][j][l]=0.0f;

    for (int kt = 0; kt < 8; kt++){
        __syncthreads();
        const long long tk = (long long)b*SS + kt*64;
        #pragma unroll
        for (int it=0; it<2; it++){
            int idx = tid + it*256;
            int r = idx >> 3, c8 = (idx & 7)*8;
            long long go = (tk+r)*3072 + 1024 + qoff + c8;
            *(uint4*)&Kh[r*LDQ + c8] = *(const uint4*)&g_qkvH[go];
            *(uint4*)&Kl[r*LDQ + c8] = *(const uint4*)&g_qkvL[go];
        }
        #pragma unroll
        for (int it=0; it<8; it++){
            int idx = tid + it*256;
            int t = idx >> 5, d = (idx & 31)*2;
            long long go = (tk+t)*3072 + 2048 + qoff + d;
            uint32_t vh = *(const uint32_t*)&g_qkvH[go];
            uint32_t vl = *(const uint32_t*)&g_qkvL[go];
            *(uint16_t*)&Vth[ d   *LDQ + t] = (uint16_t)(vh & 0xffffu);
            *(uint16_t*)&Vth[(d+1)*LDQ + t] = (uint16_t)(vh >> 16);
            *(uint16_t*)&Vtl[ d   *LDQ + t] = (uint16_t)(vl & 0xffffu);
            *(uint16_t*)&Vtl[(d+1)*LDQ + t] = (uint16_t)(vl >> 16);
        }
        __syncthreads();

        float acc_s[2][4][4];
        #pragma unroll
        for (int i=0;i<2;i++)
            #pragma unroll
            for (int j=0;j<4;j++)
                #pragma unroll
                for (int l=0;l<4;l++) acc_s[i][j][l]=0.0f;

        #pragma unroll
        for (int ko=0; ko<64; ko+=16){
            uint32_t aH[2][4], aL[2][4], bH[4][2], bL[4][2];
            #pragma unroll
            for (int ma=0; ma<2; ma++){
                int r = wm*32 + ma*16 + g;
                const bf16* ph = &Qh[r*LDQ + ko + q*2];
                const bf16* pl = &Ql[r*LDQ + ko + q*2];
                aH[ma][0]=*(const uint32_t*)ph;
                aH[ma][1]=*(const uint32_t*)(ph + 8*LDQ);
                aH[ma][2]=*(const uint32_t*)(ph + 8);
                aH[ma][3]=*(const uint32_t*)(ph + 8*LDQ + 8);
                aL[ma][0]=*(const uint32_t*)pl;
                aL[ma][1]=*(const uint32_t*)(pl + 8*LDQ);
                aL[ma][2]=*(const uint32_t*)(pl + 8);
                aL[ma][3]=*(const uint32_t*)(pl + 8*LDQ + 8);
            }
            #pragma unroll
            for (int na=0; na<4; na++){
                int c = wn*32 + na*8 + g;
                const bf16* ph = &Kh[c*LDQ + ko + q*2];
                const bf16* pl = &Kl[c*LDQ + ko + q*2];
                bH[na][0]=*(const uint32_t*)ph; bH[na][1]=*(const uint32_t*)(ph+8);
                bL[na][0]=*(const uint32_t*)pl; bL[na][1]=*(const uint32_t*)(pl+8);
            }
            #pragma unroll
            for (int ma=0; ma<2; ma++)
                #pragma unroll
                for (int na=0; na<4; na++){
                    mma16816(acc_s[ma][na], aH[ma], bH[na]);
                    mma16816(acc_s[ma][na], aH[ma], bL[na]);
                    mma16816(acc_s[ma][na], aL[ma], bH[na]);
                }
        }
        #pragma unroll
        for (int i=0;i<2;i++)
            #pragma unroll
            for (int j=0;j<4;j++)
                #pragma unroll
                for (int l=0;l<4;l++) acc_s[i][j][l] *= 0.125f;

        float rmx[2][2];
        #pragma unroll
        for (int ma=0; ma<2; ma++)
            #pragma unroll
            for (int rr=0; rr<2; rr++){
                float m = -1e30f;
                #pragma unroll
                for (int na=0; na<4; na++){
                    m = fmaxf(m, acc_s[ma][na][rr*2]);
                    m = fmaxf(m, acc_s[ma][na][rr*2+1]);
                }
                m = fmaxf(m, __shfl_xor_sync(0xffffffffu, m, 1));
                m = fmaxf(m, __shfl_xor_sync(0xffffffffu, m, 2));
                rmx[ma][rr] = m;
            }
        if (q == 0){
            #pragma unroll
            for (int ma=0; ma<2; ma++)
                #pragma unroll
                for (int rr=0; rr<2; rr++)
                    pm[wn*128 + wm*32 + ma*16 + rr*8 + g] = rmx[ma][rr];
        }
        __syncthreads();

        float mnew[2][2], sc[2][2];
        #pragma unroll
        for (int ma=0; ma<2; ma++)
            #pragma unroll
            for (int rr=0; rr<2; rr++){
                int r = wm*32 + ma*16 + rr*8 + g;
                float mo = m_s[r];
                float mn = fmaxf(mo, fmaxf(pm[r], pm[128+r]));
                mnew[ma][rr] = mn;
                sc[ma][rr] = __expf(mo - mn);
            }

        float rsm[2][2] = {{0,0},{0,0}};
        #pragma unroll
        for (int ma=0; ma<2; ma++)
            #pragma unroll
            for (int na=0; na<4; na++)
                #pragma unroll
                for (int e=0; e<4; e++){
                    int rr = e >> 1;
                    float p = __expf(acc_s[ma][na][e] - mnew[ma][rr]);
                    acc_s[ma][na][e] = p;
                    rsm[ma][rr] += p;
                }
        #pragma unroll
        for (int ma=0; ma<2; ma++)
            #pragma unroll
            for (int rr=0; rr<2; rr++){
                float s = rsm[ma][rr];
                s += __shfl_xor_sync(0xffffffffu, s, 1);
                s += __shfl_xor_sync(0xffffffffu, s, 2);
                rsm[ma][rr] = s;
            }
        if (q == 0){
            #pragma unroll
            for (int ma=0; ma<2; ma++)
                #pragma unroll
                for (int rr=0; rr<2; rr++)
                    ps[wn*128 + wm*32 + ma*16 + rr*8 + g] = rsm[ma][rr];
        }

        #pragma unroll
        for (int ma=0; ma<2; ma++){
            int r0 = wm*32 + ma*16 + g;
            #pragma unroll
            for (int na=0; na<4; na++){
                int c = wn*32 + na*8 + q*2;
                #pragma unroll
                for (int rr=0; rr<2; rr++){
                    int r = r0 + rr*8;
                    float l0, l1;
                    uint32_t phv = pack_hi(acc_s[ma][na][rr*2], acc_s[ma][na][rr*2+1], l0, l1);
                    uint32_t plv = pack_lo(l0, l1);
                    *(uint32_t*)&Ph[r*LDQ + c] = phv;
                    *(uint32_t*)&Pl[r*LDQ + c] = plv;
                }
            }
        }
        #pragma unroll
        for (int ma=0; ma<2; ma++)
            #pragma unroll
            for (int na=0; na<4; na++)
                #pragma unroll
                for (int e=0; e<4; e++) acc_o[ma][na][e] *= sc[ma][e>>1];
        __syncthreads();

        if (wn == 0 && q == 0){
            #pragma unroll
            for (int ma=0; ma<2; ma++)
                #pragma unroll
                for (int rr=0; rr<2; rr++){
                    int r = wm*32 + ma*16 + rr*8 + g;
                    l_s[r] = l_s[r]*sc[ma][rr] + ps[r] + ps[128+r];
                    m_s[r] = mnew[ma][rr];
                }
        }

        #pragma unroll
        for (int ko=0; ko<64; ko+=16){
            uint32_t aH[2][4], aL[2][4], bH[4][2], bL[4][2];
            #pragma unroll
            for (int ma=0; ma<2; ma++){
                int r = wm*32 + ma*16 + g;
                const bf16* ph = &Ph[r*LDQ + ko + q*2];
                const bf16* pl = &Pl[r*LDQ + ko + q*2];
                aH[ma][0]=*(const uint32_t*)ph;
                aH[ma][1]=*(const uint32_t*)(ph + 8*LDQ);
                aH[ma][2]=*(const uint32_t*)(ph + 8);
                aH[ma][3]=*(const uint32_t*)(ph + 8*LDQ + 8);
                aL[ma][0]=*(const uint32_t*)pl;
                aL[ma][1]=*(const uint32_t*)(pl + 8*LDQ);
                aL[ma][2]=*(const uint32_t*)(pl + 8);
                aL[ma][3]=*(const uint32_t*)(pl + 8*LDQ + 8);
            }
            #pragma unroll
            for (int na=0; na<4; na++){
                int c = wn*32 + na*8 + g;
                const bf16* ph = &Vth[c*LDQ + ko + q*2];
                const bf16* pl = &Vtl[c*LDQ + ko + q*2];
                bH[na][0]=*(const uint32_t*)ph; bH[na][1]=*(const uint32_t*)(ph+8);
                bL[na][0]=*(const uint32_t*)pl; bL[na][1]=*(const uint32_t*)(pl+8);
            }
            #pragma unroll
            for (int ma=0; ma<2; ma++)
                #pragma unroll
                for (int na=0; na<4; na++){
                    mma16816(acc_o[ma][na], aH[ma], bH[na]);
                    mma16816(acc_o[ma][na], aH[ma], bL[na]);
                    mma16816(acc_o[ma][na], aL[ma], bH[na]);
                }
        }
    }
    __syncthreads();

    #pragma unroll
    for (int ma=0; ma<2; ma++){
        int r0 = wm*32 + ma*16 + g;
        #pragma unroll
        for (int na=0; na<4; na++){
            int c = wn*32 + na*8 + q*2;
            #pragma unroll
            for (int rr=0; rr<2; rr++){
                int r = r0 + rr*8;
                float inv = 1.0f / l_s[r];
                float o0 = acc_o[ma][na][rr*2]   * inv;
                float o1 = acc_o[ma][na][rr*2+1] * inv;
                long long gi = (tb + r)*DD + qoff + c;
                float l0, l1;
                uint32_t phv = pack_hi(o0, o1, l0, l1);
                uint32_t plv = pack_lo(l0, l1);
                *(uint32_t*)&g_ctxH[gi] = phv;
                *(uint32_t*)&g_ctxL[gi] = plv;
            }
        }
    }
}

// ---------------- small kernels ----------------
__global__ void k_copy(const float* __restrict__ s, float* __restrict__ d, long long n){
    long long i = (long long)blockIdx.x*blockDim.x + threadIdx.x;
    if (i < n) d[i] = s[i];
}

__global__ void k_split(const float* __restrict__ s, bf16* __restrict__ dh,
                        bf16* __restrict__ dl, long long n){
    long long i = (long long)blockIdx.x*blockDim.x + threadIdx.x;
    if (i >= n) return;
    float v = s[i];
    bf16 h = __float2bfloat16(v);
    dh[i] = h;
    dl[i] = __float2bfloat16(v - __bfloat162float(h));
}

__global__ void k_split_cat(const float* __restrict__ s, int colOff){
    long long i = (long long)blockIdx.x*blockDim.x + threadIdx.x;
    if (i >= (long long)NTOK*DD) return;
    int t = (int)(i >> 10), j = (int)(i & 1023);
    float v = s[i];
    bf16 h = __float2bfloat16(v);
    long long di = (long long)t*2*DD + colOff + j;
    g_catH[di] = h;
    g_catL[di] = __float2bfloat16(v - __bfloat162float(h));
}

__global__ void k_pool(const float* __restrict__ h){
    int i = blockIdx.x*blockDim.x + threadIdx.x;
    if (i >= BB*DD) return;
    int b = i / DD, d = i % DD;
    const float* p = h + (long long)b*SS*DD + d;
    float s = 0.0f;
    for (int t=0;t<SS;t++) s += p[(long long)t*DD];
    g_pool[i] = s * (1.0f/(float)SS);
}

__global__ void k_sp1(const float* __restrict__ w1, const float* __restrict__ b1){
    int i = blockIdx.x*blockDim.x + threadIdx.x;
    if (i >= BB*DQ) return;
    int b = i / DQ, j = i % DQ;
    const float* p = g_pool + b*DD;
    const float* w = w1 + (long long)j*DD;
    float s = b1[j];
    for (int d=0; d<DD; d++) s = fmaf(p[d], w[d], s);
    g_sph[i] = gelu_f(s);
}

__global__ void k_init(const float* __restrict__ w2, const float* __restrict__ b2,
                       const float* __restrict__ gl){
    if (threadIdx.x != 0) return;
    float m = 0.0f;
    for (int b=0;b<BB;b++){
        float s = b2[0];
        for (int j=0;j<DQ;j++) s = fmaf(g_sph[b*DQ+j], w2[j], s);
        m += 1.0f/(1.0f + expf(-s));
    }
    m *= 1.0f/(float)BB;
    int ns = MIN_STEPS + (int)floorf(m * (float)(MAX_STEPS - MIN_STEPS));
    if (ns > MAX_STEPS) ns = MAX_STEPS;
    g_num_steps = ns;
    g_active = 1;
    float e0 = expf(gl[0]), e1 = expf(gl[1]), e2 = expf(gl[2]);
    g_gw0 = e0/(e0+e1+e2);
}

__global__ void k_begin(int i){
    if (threadIdx.x == 0){
        g_act = (g_active && (i < g_num_steps)) ? 1 : 0;
        g_red[0] = 0.0; g_red[1] = 0.0;
    }
}

__global__ void k_ln(const float* __restrict__ lg, const float* __restrict__ lb){
    if (g_act == 0) return;
    long long off = (long long)blockIdx.x * DD;
    int t = threadIdx.x;
    float u[4], hv[4];
    float sm = 0.0f;
    #pragma unroll
    for (int j=0;j<4;j++){
        int idx = t + j*256;
        hv[j] = g_h[off+idx];
        u[j]  = fmaf(g_G1[off+idx], g_phi[off+idx], hv[j]);
        sm += u[j];
    }
    sm = blockReduceSum<float>(sm);
    __shared__ float s_mean, s_inv;
    if (t==0) s_mean = sm * (1.0f/(float)DD);
    __syncthreads();
    float mean = s_mean, vs = 0.0f;
    #pragma unroll
    for (int j=0;j<4;j++){ float d = u[j]-mean; vs += d*d; }
    vs = blockReduceSum<float>(vs);
    if (t==0) s_inv = rsqrtf(vs*(1.0f/(float)DD) + 1e-5f);
    __syncthreads();
    float inv = s_inv;
    double dq = 0.0, hq = 0.0;
    long long cbase = (long long)blockIdx.x * 2*DD;
    #pragma unroll
    for (int j=0;j<4;j++){
        int idx = t + j*256;
        float y = (u[j]-mean)*inv*lg[idx] + lb[idx];
        g_h[off+idx] = y;
        bf16 hb = __float2bfloat16(y);
        g_catH[cbase+idx] = hb;
        g_catL[cbase+idx] = __float2bfloat16(y - __bfloat162float(hb));
        float df = y - hv[j];
        dq += (double)df*(double)df;
        hq += (double)hv[j]*(double)hv[j];
    }
    dq = blockReduceSum<double>(dq);
    hq = blockReduceSum<double>(hq);
    if (t==0){ atomicAdd(&g_red[0], dq); atomicAdd(&g_red[1], hq); }
}

__global__ void k_fin(int i){
    if (threadIdx.x != 0) return;
    if (g_act == 0){ g_active = 0; return; }
    double res = sqrt(g_red[0]) / (sqrt(g_red[1]) + 1e-8);
    g_active = ((i >= MIN_STEPS) && (res < 1e-4)) ? 0 : 1;
}

// ---------------- host ----------------
template<typename T>
static T* dptr(const void* symbol){
    void* p = nullptr;
    cudaGetSymbolAddress(&p, symbol);
    return (T*)p;
}

extern "C" void kernel_launch(void* const* d_in, const int* in_sizes, int n_in,
                              void* d_out, int out_size)
{
    const float* h     = (const float*)d_in[0];
    const float* x     = (const float*)d_in[1];
    const float* ig_w1 = (const float*)d_in[2];
    const float* ig_b1 = (const float*)d_in[3];
    const float* ig_w2 = (const float*)d_in[4];
    const float* ig_b2 = (const float*)d_in[5];
    const float* wq    = (const float*)d_in[6];
    const float* bq    = (const float*)d_in[7];
    const float* wk    = (const float*)d_in[8];
    const float* bk    = (const float*)d_in[9];
    const float* wv    = (const float*)d_in[10];
    const float* bv    = (const float*)d_in[11];
    const float* wo    = (const float*)d_in[12];
    const float* bo    = (const float*)d_in[13];
    const float* g1w1  = (const float*)d_in[14];
    const float* g1b1  = (const float*)d_in[15];
    const float* g1w2  = (const float*)d_in[16];
    const float* g1b2  = (const float*)d_in[17];
    const float* gl    = (const float*)d_in[18];
    const float* lng   = (const float*)d_in[19];
    const float* lnb   = (const float*)d_in[20];
    const float* spw1  = (const float*)d_in[21];
    const float* spb1  = (const float*)d_in[22];
    const float* spw2  = (const float*)d_in[23];
    const float* spb2  = (const float*)d_in[24];
    float* out = (float*)d_out;

    float* p_h    = dptr<float>(g_h);
    float* p_G1   = dptr<float>(g_G1);
    float* p_phi  = dptr<float>(g_phi);
    float* p_bqkv = dptr<float>(g_bqkv);
    bf16 *p_catH = dptr<bf16>(g_catH), *p_catL = dptr<bf16>(g_catL);
    bf16 *p_T1H  = dptr<bf16>(g_T1H),  *p_T1L  = dptr<bf16>(g_T1L);
    bf16 *p_T2H  = dptr<bf16>(g_T2H),  *p_T2L  = dptr<bf16>(g_T2L);
    bf16 *p_blnH = dptr<bf16>(g_blnH), *p_blnL = dptr<bf16>(g_blnL);
    bf16 *p_qkvH = dptr<bf16>(g_qkvH), *p_qkvL = dptr<bf16>(g_qkvL);
    bf16 *p_ctxH = dptr<bf16>(g_ctxH), *p_ctxL = dptr<bf16>(g_ctxL);
    bf16 *p_w1H  = dptr<bf16>(g_w1H),  *p_w1L  = dptr<bf16>(g_w1L);
    bf16 *p_w2H  = dptr<bf16>(g_w2H),  *p_w2L  = dptr<bf16>(g_w2L);
    bf16 *p_iw1H = dptr<bf16>(g_iw1H), *p_iw1L = dptr<bf16>(g_iw1L);
    bf16 *p_iw2H = dptr<bf16>(g_iw2H), *p_iw2L = dptr<bf16>(g_iw2L);
    bf16 *p_wqH  = dptr<bf16>(g_wqH),  *p_wqL  = dptr<bf16>(g_wqL);
    bf16 *p_woH  = dptr<bf16>(g_woH),  *p_woL  = dptr<bf16>(g_woL);

    const long long NHD = (long long)NTOK*DD;
    const long long W1  = (long long)DD*DD;

    cudaFuncSetAttribute(k_attn, cudaFuncAttributeMaxDynamicSharedMemorySize, 96*1024);

    // ---- setup
    k_copy<<<(unsigned)((NHD+255)/256),256>>>(h, p_h, NHD);
    k_split_cat<<<(unsigned)((NHD+255)/256),256>>>(h, 0);
    k_split_cat<<<(unsigned)((NHD+255)/256),256>>>(x, DD);
    k_split<<<(DQ*DD+255)/256,256>>>(g1w1,  p_w1H,  p_w1L,  DQ*DD);
    k_split<<<(DD*DQ+255)/256,256>>>(g1w2,  p_w2H,  p_w2L,  DD*DQ);
    k_split<<<(DQ*2*DD+255)/256,256>>>(ig_w1, p_iw1H, p_iw1L, DQ*2*DD);
    k_split<<<(DD*DQ+255)/256,256>>>(ig_w2, p_iw2H, p_iw2L, DD*DQ);
    k_split<<<(unsigned)((W1+255)/256),256>>>(wq, p_wqH,        p_wqL,        W1);
    k_split<<<(unsigned)((W1+255)/256),256>>>(wk, p_wqH + W1,   p_wqL + W1,   W1);
    k_split<<<(unsigned)((W1+255)/256),256>>>(wv, p_wqH + 2*W1, p_wqL + 2*W1, W1);
    k_split<<<(unsigned)((W1+255)/256),256>>>(wo, p_woH, p_woL, W1);
    k_copy<<<4,256>>>(bq, p_bqkv,        DD);
    k_copy<<<4,256>>>(bk, p_bqkv +   DD, DD);
    k_copy<<<4,256>>>(bv, p_bqkv + 2*DD, DD);
    k_pool<<<(BB*DD+255)/256,256>>>(h);
    k_sp1 <<<(BB*DQ+255)/256,256>>>(spw1, spb1);
    k_init<<<1,32>>>(spw2, spb2, gl);

    // job descriptors (constant across steps)
    GemmJob jT1 = { DD,   p_catH, p_catL, 2*DD, p_w1H,  p_w1L,  DD,   nullptr, p_T1H,  p_T1L,  DQ,   g1b1 };
    GemmJob jT2 = { 2*DD, p_catH, p_catL, 2*DD, p_iw1H, p_iw1L, 2*DD, nullptr, p_T2H,  p_T2L,  DQ,   ig_b1 };
    GemmJob jG1 = { DQ,   p_T1H,  p_T1L,  DQ,   p_w2H,  p_w2L,  DQ,   p_G1,    nullptr,nullptr,DD,   g1b2 };
    GemmJob jBL = { DQ,   p_T2H,  p_T2L,  DQ,   p_iw2H, p_iw2L, DQ,   nullptr, p_blnH, p_blnL, DD,   ig_b2 };
    GemmJob jQK = { DD,   p_blnH, p_blnL, DD,   p_wqH,  p_wqL,  DD,   nullptr, p_qkvH, p_qkvL, 3*DD, p_bqkv };
    GemmJob jPH = { DD,   p_ctxH, p_ctxL, DD,   p_woH,  p_woL,  DD,   p_phi,   nullptr,nullptr,DD,   bo };

    for (int i = 0; i < MAX_STEPS; i++){
        k_begin<<<1,32>>>(i);

        // T1 & T2 fused (z): both M2048 N256, gelu, plane-out
        gemm_dual<EPI_GELU,1,EPI_GELU,1><<<dim3(4,16,2),256>>>(jT1, jT2, nullptr, nullptr);

        // G1 & blended fused (z): both M2048 N1024 K256
        gemm_dual<EPI_GSCALE,0,EPI_BLEND,1><<<dim3(16,16,2),256>>>(jG1, jBL, p_h, x);

        // QKV: M2048 N3072 K1024
        gemm_one<EPI_NONE,1><<<dim3(48,16),256>>>(jQK, nullptr, nullptr);

        // fused flash attention -> ctx planes
        k_attn<<<dim3(4,BHN),256,96*1024>>>();

        // phi = ctx @ wo^T + bo
        gemm_one<EPI_NONE,0><<<dim3(16,16),256>>>(jPH, nullptr, nullptr);

        // h = LN(h + G1*phi) in place + residual reduction + cat planes
        k_ln<<<NTOK,256>>>(lng, lnb);
        k_fin<<<1,1>>>(i);
    }

    k_copy<<<(unsigned)((NHD+255)/256),256>>>(p_h, out, NHD);
    (void)in_sizes; (void)n_in; (void)out_size;
}

// round 6
// speedup vs baseline: 2.6242x; 1.1083x over previous
#include <cuda_runtime.h>
#include <cuda_bf16.h>
#include <math.h>
#include <stdint.h>

// ---------------- problem constants ----------------
#define BB 4
#define SS 512
#define DD 1024
#define HH 16
#define DHD 64
#define DQ 256
#define NTOK (BB*SS)            // 2048
#define BHN (BB*HH)             // 64
#define MIN_STEPS 4
#define MAX_STEPS 12

typedef __nv_bfloat16 bf16;

// ---------------- device state ----------------
__device__ int    g_act;
__device__ int    g_active;
__device__ int    g_num_steps;
__device__ float  g_gw0;
__device__ double g_red[2];

// fp32 buffers
__device__ float g_h   [NTOK*DD];
__device__ float g_G1  [NTOK*DD];
__device__ float g_phi [NTOK*DD];
__device__ float g_bqkv[3*DD];
__device__ float g_pool[BB*DD];
__device__ float g_sph [BB*DQ];

// split bf16 planes (hi / lo)
__device__ bf16 g_catH [NTOK*2*DD], g_catL [NTOK*2*DD];     // [h | x]
__device__ bf16 g_T1H  [NTOK*DQ],   g_T1L  [NTOK*DQ];
__device__ bf16 g_T2H  [NTOK*DQ],   g_T2L  [NTOK*DQ];
__device__ bf16 g_blnH [NTOK*DD],   g_blnL [NTOK*DD];
__device__ bf16 g_qkvH [NTOK*3*DD], g_qkvL [NTOK*3*DD];
__device__ bf16 g_ctxH [NTOK*DD],   g_ctxL [NTOK*DD];
// weight planes
__device__ bf16 g_w1H [DQ*DD],    g_w1L [DQ*DD];
__device__ bf16 g_w2H [DD*DQ],    g_w2L [DD*DQ];
__device__ bf16 g_iw1H[DQ*2*DD],  g_iw1L[DQ*2*DD];
__device__ bf16 g_iw2H[DD*DQ],    g_iw2L[DD*DQ];
__device__ bf16 g_wqH [3*DD*DD],  g_wqL [3*DD*DD];
__device__ bf16 g_woH [DD*DD],    g_woL [DD*DD];

// ---------------- scalar helpers ----------------
__device__ __forceinline__ float gelu_f(float v){ return 0.5f*v*(1.0f+erff(v*0.70710678118654752f)); }
__device__ __forceinline__ float sig_f (float v){ return 1.0f/(1.0f+__expf(-v)); }

__device__ __forceinline__ uint32_t pack_hi(float v0, float v1, float& r0, float& r1){
    bf16 h0 = __float2bfloat16(v0), h1 = __float2bfloat16(v1);
    r0 = v0 - __bfloat162float(h0);
    r1 = v1 - __bfloat162float(h1);
    return (uint32_t)__bfloat16_as_ushort(h0) | ((uint32_t)__bfloat16_as_ushort(h1) << 16);
}
__device__ __forceinline__ uint32_t pack_lo(float r0, float r1){
    return (uint32_t)__bfloat16_as_ushort(__float2bfloat16(r0)) |
           ((uint32_t)__bfloat16_as_ushort(__float2bfloat16(r1)) << 16);
}

template<typename T>
__device__ __forceinline__ T blockReduceSum(T v){
    static __shared__ T sh[32];
    int lane = threadIdx.x & 31, w = threadIdx.x >> 5;
    #pragma unroll
    for (int o = 16; o; o >>= 1) v += __shfl_down_sync(0xffffffffu, v, o);
    __syncthreads();
    if (lane == 0) sh[w] = v;
    __syncthreads();
    T r = (T)0;
    if (w == 0){
        int nw = (blockDim.x + 31) >> 5;
        r = (lane < nw) ? sh[lane] : (T)0;
        #pragma unroll
        for (int o = 16; o; o >>= 1) r += __shfl_down_sync(0xffffffffu, r, o);
    }
    return r;
}

__device__ __forceinline__ uint32_t s2u(const void* p){
    uint32_t a;
    asm("{ .reg .u64 t; cvta.to.shared.u64 t, %1; cvt.u32.u64 %0, t; }" : "=r"(a) : "l"(p));
    return a;
}
#define CPA16(d,s) asm volatile("cp.async.cg.shared.global [%0], [%1], 16;\n" :: "r"(d), "l"(s))
#define CPCOMMIT() asm volatile("cp.async.commit_group;\n" ::: "memory")
__device__ __forceinline__ void cpwait1(){ asm volatile("cp.async.wait_group 1;\n" ::: "memory"); }
__device__ __forceinline__ void cpwait0(){ asm volatile("cp.async.wait_group 0;\n" ::: "memory"); }

__device__ __forceinline__ void mma16816(float* c, const uint32_t* a, const uint32_t* b){
    asm volatile(
        "mma.sync.aligned.m16n8k16.row.col.f32.bf16.bf16.f32 "
        "{%0,%1,%2,%3}, {%4,%5,%6,%7}, {%8,%9}, {%0,%1,%2,%3};\n"
        : "+f"(c[0]), "+f"(c[1]), "+f"(c[2]), "+f"(c[3])
        : "r"(a[0]), "r"(a[1]), "r"(a[2]), "r"(a[3]), "r"(b[0]), "r"(b[1]));
}
__device__ __forceinline__ void ldsm4(uint32_t* r, uint32_t addr){
    asm volatile("ldmatrix.sync.aligned.m8n8.x4.shared.b16 {%0,%1,%2,%3}, [%4];"
        : "=r"(r[0]), "=r"(r[1]), "=r"(r[2]), "=r"(r[3]) : "r"(addr));
}
__device__ __forceinline__ void ldsm4t(uint32_t* r, uint32_t addr){
    asm volatile("ldmatrix.sync.aligned.m8n8.x4.trans.shared.b16 {%0,%1,%2,%3}, [%4];"
        : "=r"(r[0]), "=r"(r[1]), "=r"(r[2]), "=r"(r[3]) : "r"(addr));
}

// ---------------- pipelined split-bf16 HMMA NT GEMM core -------------------
enum { EPI_NONE=0, EPI_GELU=1, EPI_BLEND=3, EPI_GSCALE=4 };

struct GemmJob {
    int K;
    const bf16 *Ah, *Al; int lda;
    const bf16 *Bh, *Bl; int ldb;
    float* Cf; bf16 *Ch, *Cl; int ldc;
    const float* bias;
};

#define GBM 128
#define GBN 64
#define GBK 32
#define GLDK 40
#define STG_BYTES 30720
#define OFF_AL 10240u
#define OFF_BH 20480u
#define OFF_BL 25600u

template<int EPI,int WM>
__device__ __forceinline__ void gemm_core(const GemmJob J, char* buf,
                                          const float* Hp, const float* Xp)
{
    const int tid  = threadIdx.x;
    const int lane = tid & 31;
    const int wid  = tid >> 5;
    const int wm   = wid >> 1;
    const int wn   = wid & 1;
    const int g    = lane >> 2;
    const int q    = lane & 3;
    const int rm = blockIdx.y * GBM;
    const int cn = blockIdx.x * GBN;
    const uint32_t sb = s2u(buf);

    // ldmatrix lane geometry (elements)
    const int aRow = wm*32 + (lane & 15);
    const int aK   = (lane >> 4) << 3;
    const int bRow = wn*32 + ((lane >> 4) << 3) + (lane & 7);
    const int bK   = ((lane >> 3) & 1) << 3;

    auto stg = [&](int st, int kt){
        uint32_t sa = sb + (uint32_t)st * STG_BYTES;
        #pragma unroll
        for (int it=0; it<2; it++){
            int idx = tid + it*256;
            int row = idx >> 2;
            int c8  = (idx & 3) * 8;
            size_t go = (size_t)(rm+row)*J.lda + kt + c8;
            uint32_t d = sa + (uint32_t)(row*GLDK + c8)*2;
            CPA16(d,          J.Ah + go);
            CPA16(d + OFF_AL, J.Al + go);
        }
        {
            int row = tid >> 2;
            int c8  = (tid & 3) * 8;
            size_t go = (size_t)(cn+row)*J.ldb + kt + c8;
            uint32_t d = sa + OFF_BH + (uint32_t)(row*GLDK + c8)*2;
            CPA16(d,                    J.Bh + go);
            CPA16(d + (OFF_BL-OFF_BH),  J.Bl + go);
        }
        CPCOMMIT();
    };

    float acc[2][4][4];
    #pragma unroll
    for (int i=0;i<2;i++)
        #pragma unroll
        for (int j=0;j<4;j++)
            #pragma unroll
            for (int l=0;l<4;l++) acc[i][j][l] = 0.0f;

    const int niter = J.K / GBK;
    stg(0, 0);
    stg(1, GBK);

    for (int i=0; i<niter; i++){
        const int st = i & 1;
        const uint32_t sAh = sb + (uint32_t)st*STG_BYTES;
        const uint32_t sAl = sAh + OFF_AL;
        const uint32_t sBh = sAh + OFF_BH;
        const uint32_t sBl = sAh + OFF_BL;

        if (i+1 < niter) cpwait1(); else cpwait0();
        __syncthreads();

        #pragma unroll
        for (int ks=0; ks<2; ks++){
            const int ko = ks*16;
            uint32_t aH[2][4], aL[2][4], bH[2][4], bL[2][4];
            #pragma unroll
            for (int ma=0; ma<2; ma++){
                uint32_t off = (uint32_t)((aRow + ma*16)*GLDK + ko + aK)*2;
                ldsm4(aH[ma], sAh + off);
                ldsm4(aL[ma], sAl + off);
            }
            #pragma unroll
            for (int g2=0; g2<2; g2++){
                uint32_t off = (uint32_t)((bRow + g2*16)*GLDK + ko + bK)*2;
                ldsm4(bH[g2], sBh + off);
                ldsm4(bL[g2], sBl + off);
            }
            #pragma unroll
            for (int ma=0; ma<2; ma++)
                #pragma unroll
                for (int na=0; na<4; na++){
                    const uint32_t* bh = &bH[na>>1][(na&1)*2];
                    const uint32_t* bl = &bL[na>>1][(na&1)*2];
                    mma16816(acc[ma][na], aH[ma], bh);
                    mma16816(acc[ma][na], aH[ma], bl);
                    mma16816(acc[ma][na], aL[ma], bh);
                }
        }
        __syncthreads();
        if (i+2 < niter) stg(st, (i+2)*GBK);
    }

    // epilogue
    #pragma unroll
    for (int ma=0; ma<2; ma++){
        int r0 = rm + wm*32 + ma*16 + g;
        #pragma unroll
        for (int na=0; na<4; na++){
            int c = cn + wn*32 + na*8 + q*2;
            #pragma unroll
            for (int hrow=0; hrow<2; hrow++){
                int r = r0 + hrow*8;
                long long gi = (long long)r*J.ldc + c;
                float v[2];
                #pragma unroll
                for (int e=0; e<2; e++){
                    float t = acc[ma][na][hrow*2+e];
                    if (J.bias) t += J.bias[c+e];
                    if      (EPI==EPI_GELU)   t = gelu_f(t);
                    else if (EPI==EPI_GSCALE) t = sig_f(t) * g_gw0;
                    else if (EPI==EPI_BLEND){
                        float s = sig_f(t);
                        t = s*Hp[gi+e] + (1.0f - s)*Xp[gi+e];
                    }
                    v[e] = t;
                }
                if (WM == 0){
                    J.Cf[gi] = v[0]; J.Cf[gi+1] = v[1];
                } else {
                    float r0f, r1f;
                    uint32_t ph = pack_hi(v[0], v[1], r0f, r1f);
                    uint32_t pl = pack_lo(r0f, r1f);
                    *(uint32_t*)&J.Ch[gi] = ph;
                    *(uint32_t*)&J.Cl[gi] = pl;
                }
            }
        }
    }
}

template<int EPI,int WM>
__global__ void __launch_bounds__(256)
gemm_one(GemmJob J, const float* Hp, const float* Xp){
    if (g_act == 0) return;
    __shared__ char buf[2*STG_BYTES];
    gemm_core<EPI,WM>(J, buf, Hp, Xp);
}

template<int E0,int W0,int E1,int W1>
__global__ void __launch_bounds__(256)
gemm_dual(GemmJob J0, GemmJob J1, const float* Hp, const float* Xp){
    if (g_act == 0) return;
    __shared__ char buf[2*STG_BYTES];
    if (blockIdx.z == 0) gemm_core<E0,W0>(J0, buf, Hp, Xp);
    else                 gemm_core<E1,W1>(J1, buf, Hp, Xp);
}

// ---------------- fused flash attention (ldmatrix everywhere) -------------
// smem: Qh 0 (18432) Ql 18432 | Kh 36864(9216) Kl 46080 | Ph 36864 (18432, reuses K)
//       Vh 55296(9216) Vl 64512 | Pl 73728(18432) | floats 92160
#define LDQ 72
#define ATT_SMEM (92160 + 3072)
__global__ void __launch_bounds__(256) k_attn(void){
    if (g_act == 0) return;
    extern __shared__ char sm_[];
    bf16* Qh = (bf16*)(sm_);
    bf16* Ql = (bf16*)(sm_ + 18432);
    bf16* Kh = (bf16*)(sm_ + 36864);
    bf16* Kl = (bf16*)(sm_ + 46080);
    bf16* Ph = (bf16*)(sm_ + 36864);
    bf16* Vh = (bf16*)(sm_ + 55296);
    bf16* Vl = (bf16*)(sm_ + 64512);
    bf16* Pl = (bf16*)(sm_ + 73728);
    float* pm  = (float*)(sm_ + 92160);
    float* ps  = pm + 256;
    float* m_s = ps + 256;
    float* l_s = m_s + 128;

    const int tid  = threadIdx.x;
    const int lane = tid & 31;
    const int wid  = tid >> 5;
    const int wm   = wid >> 1;
    const int wn   = wid & 1;
    const int g    = lane >> 2;
    const int q    = lane & 3;

    const int qt = blockIdx.x;
    const int bh = blockIdx.y;
    const int b  = bh >> 4, hh = bh & 15;
    const long long tb = (long long)b*SS + qt*128;
    const int qoff = hh*64;

    const uint32_t sQh = s2u(sm_), sQl = sQh + 18432u;
    const uint32_t sKh = sQh + 36864u, sKl = sQh + 46080u;
    const uint32_t sPh = sQh + 36864u, sPl = sQh + 73728u;
    const uint32_t sVh = sQh + 55296u, sVl = sQh + 64512u;

    // ldmatrix lane geometry
    const int aRow = wm*32 + (lane & 15);           // A-type (Q, P)
    const int aK   = (lane >> 4) << 3;
    const int bRow = wn*32 + ((lane >> 4) << 3) + (lane & 7);   // B-type (K)
    const int bK   = ((lane >> 3) & 1) << 3;
    const int vT   = (lane & 7) + (((lane >> 3) & 1) << 3);     // B-trans (V)
    const int vD   = wn*32 + ((lane >> 4) << 3);

    if (tid < 128){ m_s[tid] = -1e30f; l_s[tid] = 0.0f; }

    #pragma unroll
    for (int it=0; it<4; it++){
        int idx = tid + it*256;
        int r = idx >> 3, c8 = (idx & 7)*8;
        long long go = (tb+r)*3072 + qoff + c8;
        *(uint4*)&Qh[r*LDQ + c8] = *(const uint4*)&g_qkvH[go];
        *(uint4*)&Ql[r*LDQ + c8] = *(const uint4*)&g_qkvL[go];
    }

    float acc_o[2][4][4];
    #pragma unroll
    for (int i=0;i<2;i++)
        #pragma unroll
        for (int j=0;j<4;j++)
            #pragma unroll
            for (int l=0;l<4;l++) acc_o[i][j][l]=0.0f;

    for (int kt = 0; kt < 8; kt++){
        __syncthreads();   // prev PV done (P reuses K region), Q staged (iter 0)
        const long long tk = (long long)b*SS + kt*64;
        #pragma unroll
        for (int it=0; it<2; it++){
            int idx = tid + it*256;
            int r = idx >> 3, c8 = (idx & 7)*8;
            long long goK = (tk+r)*3072 + 1024 + qoff + c8;
            long long goV = (tk+r)*3072 + 2048 + qoff + c8;
            *(uint4*)&Kh[r*LDQ + c8] = *(const uint4*)&g_qkvH[goK];
            *(uint4*)&Kl[r*LDQ + c8] = *(const uint4*)&g_qkvL[goK];
            *(uint4*)&Vh[r*LDQ + c8] = *(const uint4*)&g_qkvH[goV];
            *(uint4*)&Vl[r*LDQ + c8] = *(const uint4*)&g_qkvL[goV];
        }
        __syncthreads();

        // ---- S = Q @ K^T
        float acc_s[2][4][4];
        #pragma unroll
        for (int i=0;i<2;i++)
            #pragma unroll
            for (int j=0;j<4;j++)
                #pragma unroll
                for (int l=0;l<4;l++) acc_s[i][j][l]=0.0f;

        #pragma unroll
        for (int ko=0; ko<64; ko+=16){
            uint32_t aH[2][4], aL[2][4], bH[2][4], bL[2][4];
            #pragma unroll
            for (int ma=0; ma<2; ma++){
                uint32_t off = (uint32_t)((aRow + ma*16)*LDQ + ko + aK)*2;
                ldsm4(aH[ma], sQh + off);
                ldsm4(aL[ma], sQl + off);
            }
            #pragma unroll
            for (int g2=0; g2<2; g2++){
                uint32_t off = (uint32_t)((bRow + g2*16)*LDQ + ko + bK)*2;
                ldsm4(bH[g2], sKh + off);
                ldsm4(bL[g2], sKl + off);
            }
            #pragma unroll
            for (int ma=0; ma<2; ma++)
                #pragma unroll
                for (int na=0; na<4; na++){
                    const uint32_t* bhp = &bH[na>>1][(na&1)*2];
                    const uint32_t* blp = &bL[na>>1][(na&1)*2];
                    mma16816(acc_s[ma][na], aH[ma], bhp);
                    mma16816(acc_s[ma][na], aH[ma], blp);
                    mma16816(acc_s[ma][na], aL[ma], bhp);
                }
        }
        #pragma unroll
        for (int i=0;i<2;i++)
            #pragma unroll
            for (int j=0;j<4;j++)
                #pragma unroll
                for (int l=0;l<4;l++) acc_s[i][j][l] *= 0.125f;

        // ---- online softmax
        float rmx[2][2];
        #pragma unroll
        for (int ma=0; ma<2; ma++)
            #pragma unroll
            for (int rr=0; rr<2; rr++){
                float m = -1e30f;
                #pragma unroll
                for (int na=0; na<4; na++){
                    m = fmaxf(m, acc_s[ma][na][rr*2]);
                    m = fmaxf(m, acc_s[ma][na][rr*2+1]);
                }
                m = fmaxf(m, __shfl_xor_sync(0xffffffffu, m, 1));
                m = fmaxf(m, __shfl_xor_sync(0xffffffffu, m, 2));
                rmx[ma][rr] = m;
            }
        if (q == 0){
            #pragma unroll
            for (int ma=0; ma<2; ma++)
                #pragma unroll
                for (int rr=0; rr<2; rr++)
                    pm[wn*128 + wm*32 + ma*16 + rr*8 + g] = rmx[ma][rr];
        }
        __syncthreads();   // also: all S-MMA reads of K done before P overwrites it

        float mnew[2][2], sc[2][2];
        #pragma unroll
        for (int ma=0; ma<2; ma++)
            #pragma unroll
            for (int rr=0; rr<2; rr++){
                int r = wm*32 + ma*16 + rr*8 + g;
                float mo = m_s[r];
                float mn = fmaxf(mo, fmaxf(pm[r], pm[128+r]));
                mnew[ma][rr] = mn;
                sc[ma][rr] = __expf(mo - mn);
            }

        float rsm[2][2] = {{0,0},{0,0}};
        #pragma unroll
        for (int ma=0; ma<2; ma++)
            #pragma unroll
            for (int na=0; na<4; na++)
                #pragma unroll
                for (int e=0; e<4; e++){
                    int rr = e >> 1;
                    float p = __expf(acc_s[ma][na][e] - mnew[ma][rr]);
                    acc_s[ma][na][e] = p;
                    rsm[ma][rr] += p;
                }
        #pragma unroll
        for (int ma=0; ma<2; ma++)
            #pragma unroll
            for (int rr=0; rr<2; rr++){
                float s = rsm[ma][rr];
                s += __shfl_xor_sync(0xffffffffu, s, 1);
                s += __shfl_xor_sync(0xffffffffu, s, 2);
                rsm[ma][rr] = s;
            }
        if (q == 0){
            #pragma unroll
            for (int ma=0; ma<2; ma++)
                #pragma unroll
                for (int rr=0; rr<2; rr++)
                    ps[wn*128 + wm*32 + ma*16 + rr*8 + g] = rsm[ma][rr];
        }

        // write P split planes
        #pragma unroll
        for (int ma=0; ma<2; ma++){
            int r0 = wm*32 + ma*16 + g;
            #pragma unroll
            for (int na=0; na<4; na++){
                int c = wn*32 + na*8 + q*2;
                #pragma unroll
                for (int rr=0; rr<2; rr++){
                    int r = r0 + rr*8;
                    float l0, l1;
                    uint32_t phv = pack_hi(acc_s[ma][na][rr*2], acc_s[ma][na][rr*2+1], l0, l1);
                    uint32_t plv = pack_lo(l0, l1);
                    *(uint32_t*)&Ph[r*LDQ + c] = phv;
                    *(uint32_t*)&Pl[r*LDQ + c] = plv;
                }
            }
        }
        #pragma unroll
        for (int ma=0; ma<2; ma++)
            #pragma unroll
            for (int na=0; na<4; na++)
                #pragma unroll
                for (int e=0; e<4; e++) acc_o[ma][na][e] *= sc[ma][e>>1];
        __syncthreads();

        if (wn == 0 && q == 0){
            #pragma unroll
            for (int ma=0; ma<2; ma++)
                #pragma unroll
                for (int rr=0; rr<2; rr++){
                    int r = wm*32 + ma*16 + rr*8 + g;
                    l_s[r] = l_s[r]*sc[ma][rr] + ps[r] + ps[128+r];
                    m_s[r] = mnew[ma][rr];
                }
        }

        // ---- O += P @ V  (V via ldmatrix.trans from natural [t][d] layout)
        #pragma unroll
        for (int ko=0; ko<64; ko+=16){
            uint32_t aH[2][4], aL[2][4], bH[2][4], bL[2][4];
            #pragma unroll
            for (int ma=0; ma<2; ma++){
                uint32_t off = (uint32_t)((aRow + ma*16)*LDQ + ko + aK)*2;
                ldsm4(aH[ma], sPh + off);
                ldsm4(aL[ma], sPl + off);
            }
            #pragma unroll
            for (int g2=0; g2<2; g2++){
                uint32_t off = (uint32_t)((ko + vT)*LDQ + vD + g2*16 + ((lane>>4)<<3)*0)*2;
                // columns: vD already includes (lane>>4)<<3; add g2*16
                ldsm4t(bH[g2], sVh + off);
                ldsm4t(bL[g2], sVl + off);
            }
            #pragma unroll
            for (int ma=0; ma<2; ma++)
                #pragma unroll
                for (int na=0; na<4; na++){
                    const uint32_t* bhp = &bH[na>>1][(na&1)*2];
                    const uint32_t* blp = &bL[na>>1][(na&1)*2];
                    mma16816(acc_o[ma][na], aH[ma], bhp);
                    mma16816(acc_o[ma][na], aH[ma], blp);
                    mma16816(acc_o[ma][na], aL[ma], bhp);
                }
        }
    }
    __syncthreads();

    // epilogue
    #pragma unroll
    for (int ma=0; ma<2; ma++){
        int r0 = wm*32 + ma*16 + g;
        #pragma unroll
        for (int na=0; na<4; na++){
            int c = wn*32 + na*8 + q*2;
            #pragma unroll
            for (int rr=0; rr<2; rr++){
                int r = r0 + rr*8;
                float inv = 1.0f / l_s[r];
                float o0 = acc_o[ma][na][rr*2]   * inv;
                float o1 = acc_o[ma][na][rr*2+1] * inv;
                long long gi = (tb + r)*DD + qoff + c;
                float l0, l1;
                uint32_t phv = pack_hi(o0, o1, l0, l1);
                uint32_t plv = pack_lo(l0, l1);
                *(uint32_t*)&g_ctxH[gi] = phv;
                *(uint32_t*)&g_ctxL[gi] = plv;
            }
        }
    }
}

// ---------------- small kernels ----------------
__global__ void k_copy(const float* __restrict__ s, float* __restrict__ d, long long n){
    long long i = (long long)blockIdx.x*blockDim.x + threadIdx.x;
    if (i < n) d[i] = s[i];
}

__global__ void k_split(const float* __restrict__ s, bf16* __restrict__ dh,
                        bf16* __restrict__ dl, long long n){
    long long i = (long long)blockIdx.x*blockDim.x + threadIdx.x;
    if (i >= n) return;
    float v = s[i];
    bf16 h = __float2bfloat16(v);
    dh[i] = h;
    dl[i] = __float2bfloat16(v - __bfloat162float(h));
}

__global__ void k_split_cat(const float* __restrict__ s, int colOff){
    long long i = (long long)blockIdx.x*blockDim.x + threadIdx.x;
    if (i >= (long long)NTOK*DD) return;
    int t = (int)(i >> 10), j = (int)(i & 1023);
    float v = s[i];
    bf16 h = __float2bfloat16(v);
    long long di = (long long)t*2*DD + colOff + j;
    g_catH[di] = h;
    g_catL[di] = __float2bfloat16(v - __bfloat162float(h));
}

__global__ void k_pool(const float* __restrict__ h){
    int i = blockIdx.x*blockDim.x + threadIdx.x;
    if (i >= BB*DD) return;
    int b = i / DD, d = i % DD;
    const float* p = h + (long long)b*SS*DD + d;
    float s = 0.0f;
    for (int t=0;t<SS;t++) s += p[(long long)t*DD];
    g_pool[i] = s * (1.0f/(float)SS);
}

__global__ void k_sp1(const float* __restrict__ w1, const float* __restrict__ b1){
    int i = blockIdx.x*blockDim.x + threadIdx.x;
    if (i >= BB*DQ) return;
    int b = i / DQ, j = i % DQ;
    const float* p = g_pool + b*DD;
    const float* w = w1 + (long long)j*DD;
    float s = b1[j];
    for (int d=0; d<DD; d++) s = fmaf(p[d], w[d], s);
    g_sph[i] = gelu_f(s);
}

__global__ void k_init(const float* __restrict__ w2, const float* __restrict__ b2,
                       const float* __restrict__ gl){
    if (threadIdx.x != 0) return;
    float m = 0.0f;
    for (int b=0;b<BB;b++){
        float s = b2[0];
        for (int j=0;j<DQ;j++) s = fmaf(g_sph[b*DQ+j], w2[j], s);
        m += 1.0f/(1.0f + expf(-s));
    }
    m *= 1.0f/(float)BB;
    int ns = MIN_STEPS + (int)floorf(m * (float)(MAX_STEPS - MIN_STEPS));
    if (ns > MAX_STEPS) ns = MAX_STEPS;
    g_num_steps = ns;
    g_active = 1;
    float e0 = expf(gl[0]), e1 = expf(gl[1]), e2 = expf(gl[2]);
    g_gw0 = e0/(e0+e1+e2);
}

__global__ void k_begin(int i){
    if (threadIdx.x == 0){
        g_act = (g_active && (i < g_num_steps)) ? 1 : 0;
        g_red[0] = 0.0; g_red[1] = 0.0;
    }
}

__global__ void k_ln(const float* __restrict__ lg, const float* __restrict__ lb){
    if (g_act == 0) return;
    long long off = (long long)blockIdx.x * DD;
    int t = threadIdx.x;
    float u[4], hv[4];
    float sm = 0.0f;
    #pragma unroll
    for (int j=0;j<4;j++){
        int idx = t + j*256;
        hv[j] = g_h[off+idx];
        u[j]  = fmaf(g_G1[off+idx], g_phi[off+idx], hv[j]);
        sm += u[j];
    }
    sm = blockReduceSum<float>(sm);
    __shared__ float s_mean, s_inv;
    if (t==0) s_mean = sm * (1.0f/(float)DD);
    __syncthreads();
    float mean = s_mean, vs = 0.0f;
    #pragma unroll
    for (int j=0;j<4;j++){ float d = u[j]-mean; vs += d*d; }
    vs = blockReduceSum<float>(vs);
    if (t==0) s_inv = rsqrtf(vs*(1.0f/(float)DD) + 1e-5f);
    __syncthreads();
    float inv = s_inv;
    double dq = 0.0, hq = 0.0;
    long long cbase = (long long)blockIdx.x * 2*DD;
    #pragma unroll
    for (int j=0;j<4;j++){
        int idx = t + j*256;
        float y = (u[j]-mean)*inv*lg[idx] + lb[idx];
        g_h[off+idx] = y;
        bf16 hb = __float2bfloat16(y);
        g_catH[cbase+idx] = hb;
        g_catL[cbase+idx] = __float2bfloat16(y - __bfloat162float(hb));
        float df = y - hv[j];
        dq += (double)df*(double)df;
        hq += (double)hv[j]*(double)hv[j];
    }
    dq = blockReduceSum<double>(dq);
    hq = blockReduceSum<double>(hq);
    if (t==0){ atomicAdd(&g_red[0], dq); atomicAdd(&g_red[1], hq); }
}

__global__ void k_fin(int i){
    if (threadIdx.x != 0) return;
    if (g_act == 0){ g_active = 0; return; }
    double res = sqrt(g_red[0]) / (sqrt(g_red[1]) + 1e-8);
    g_active = ((i >= MIN_STEPS) && (res < 1e-4)) ? 0 : 1;
}

// ---------------- host ----------------
template<typename T>
static T* dptr(const void* symbol){
    void* p = nullptr;
    cudaGetSymbolAddress(&p, symbol);
    return (T*)p;
}

extern "C" void kernel_launch(void* const* d_in, const int* in_sizes, int n_in,
                              void* d_out, int out_size)
{
    const float* h     = (const float*)d_in[0];
    const float* x     = (const float*)d_in[1];
    const float* ig_w1 = (const float*)d_in[2];
    const float* ig_b1 = (const float*)d_in[3];
    const float* ig_w2 = (const float*)d_in[4];
    const float* ig_b2 = (const float*)d_in[5];
    const float* wq    = (const float*)d_in[6];
    const float* bq    = (const float*)d_in[7];
    const float* wk    = (const float*)d_in[8];
    const float* bk    = (const float*)d_in[9];
    const float* wv    = (const float*)d_in[10];
    const float* bv    = (const float*)d_in[11];
    const float* wo    = (const float*)d_in[12];
    const float* bo    = (const float*)d_in[13];
    const float* g1w1  = (const float*)d_in[14];
    const float* g1b1  = (const float*)d_in[15];
    const float* g1w2  = (const float*)d_in[16];
    const float* g1b2  = (const float*)d_in[17];
    const float* gl    = (const float*)d_in[18];
    const float* lng   = (const float*)d_in[19];
    const float* lnb   = (const float*)d_in[20];
    const float* spw1  = (const float*)d_in[21];
    const float* spb1  = (const float*)d_in[22];
    const float* spw2  = (const float*)d_in[23];
    const float* spb2  = (const float*)d_in[24];
    float* out = (float*)d_out;

    float* p_h    = dptr<float>(g_h);
    float* p_G1   = dptr<float>(g_G1);
    float* p_phi  = dptr<float>(g_phi);
    float* p_bqkv = dptr<float>(g_bqkv);
    bf16 *p_catH = dptr<bf16>(g_catH), *p_catL = dptr<bf16>(g_catL);
    bf16 *p_T1H  = dptr<bf16>(g_T1H),  *p_T1L  = dptr<bf16>(g_T1L);
    bf16 *p_T2H  = dptr<bf16>(g_T2H),  *p_T2L  = dptr<bf16>(g_T2L);
    bf16 *p_blnH = dptr<bf16>(g_blnH), *p_blnL = dptr<bf16>(g_blnL);
    bf16 *p_qkvH = dptr<bf16>(g_qkvH), *p_qkvL = dptr<bf16>(g_qkvL);
    bf16 *p_ctxH = dptr<bf16>(g_ctxH), *p_ctxL = dptr<bf16>(g_ctxL);
    bf16 *p_w1H  = dptr<bf16>(g_w1H),  *p_w1L  = dptr<bf16>(g_w1L);
    bf16 *p_w2H  = dptr<bf16>(g_w2H),  *p_w2L  = dptr<bf16>(g_w2L);
    bf16 *p_iw1H = dptr<bf16>(g_iw1H), *p_iw1L = dptr<bf16>(g_iw1L);
    bf16 *p_iw2H = dptr<bf16>(g_iw2H), *p_iw2L = dptr<bf16>(g_iw2L);
    bf16 *p_wqH  = dptr<bf16>(g_wqH),  *p_wqL  = dptr<bf16>(g_wqL);
    bf16 *p_woH  = dptr<bf16>(g_woH),  *p_woL  = dptr<bf16>(g_woL);

    const long long NHD = (long long)NTOK*DD;
    const long long W1  = (long long)DD*DD;

    cudaFuncSetAttribute(k_attn, cudaFuncAttributeMaxDynamicSharedMemorySize, ATT_SMEM);

    // ---- setup
    k_copy<<<(unsigned)((NHD+255)/256),256>>>(h, p_h, NHD);
    k_split_cat<<<(unsigned)((NHD+255)/256),256>>>(h, 0);
    k_split_cat<<<(unsigned)((NHD+255)/256),256>>>(x, DD);
    k_split<<<(DQ*DD+255)/256,256>>>(g1w1,  p_w1H,  p_w1L,  DQ*DD);
    k_split<<<(DD*DQ+255)/256,256>>>(g1w2,  p_w2H,  p_w2L,  DD*DQ);
    k_split<<<(DQ*2*DD+255)/256,256>>>(ig_w1, p_iw1H, p_iw1L, DQ*2*DD);
    k_split<<<(DD*DQ+255)/256,256>>>(ig_w2, p_iw2H, p_iw2L, DD*DQ);
    k_split<<<(unsigned)((W1+255)/256),256>>>(wq, p_wqH,        p_wqL,        W1);
    k_split<<<(unsigned)((W1+255)/256),256>>>(wk, p_wqH + W1,   p_wqL + W1,   W1);
    k_split<<<(unsigned)((W1+255)/256),256>>>(wv, p_wqH + 2*W1, p_wqL + 2*W1, W1);
    k_split<<<(unsigned)((W1+255)/256),256>>>(wo, p_woH, p_woL, W1);
    k_copy<<<4,256>>>(bq, p_bqkv,        DD);
    k_copy<<<4,256>>>(bk, p_bqkv +   DD, DD);
    k_copy<<<4,256>>>(bv, p_bqkv + 2*DD, DD);
    k_pool<<<(BB*DD+255)/256,256>>>(h);
    k_sp1 <<<(BB*DQ+255)/256,256>>>(spw1, spb1);
    k_init<<<1,32>>>(spw2, spb2, gl);

    GemmJob jT1 = { DD,   p_catH, p_catL, 2*DD, p_w1H,  p_w1L,  DD,   nullptr, p_T1H,  p_T1L,  DQ,   g1b1 };
    GemmJob jT2 = { 2*DD, p_catH, p_catL, 2*DD, p_iw1H, p_iw1L, 2*DD, nullptr, p_T2H,  p_T2L,  DQ,   ig_b1 };
    GemmJob jG1 = { DQ,   p_T1H,  p_T1L,  DQ,   p_w2H,  p_w2L,  DQ,   p_G1,    nullptr,nullptr,DD,   g1b2 };
    GemmJob jBL = { DQ,   p_T2H,  p_T2L,  DQ,   p_iw2H, p_iw2L, DQ,   nullptr, p_blnH, p_blnL, DD,   ig_b2 };
    GemmJob jQK = { DD,   p_blnH, p_blnL, DD,   p_wqH,  p_wqL,  DD,   nullptr, p_qkvH, p_qkvL, 3*DD, p_bqkv };
    GemmJob jPH = { DD,   p_ctxH, p_ctxL, DD,   p_woH,  p_woL,  DD,   p_phi,   nullptr,nullptr,DD,   bo };

    for (int i = 0; i < MAX_STEPS; i++){
        k_begin<<<1,32>>>(i);

        gemm_dual<EPI_GELU,1,EPI_GELU,1><<<dim3(4,16,2),256>>>(jT1, jT2, nullptr, nullptr);
        gemm_dual<EPI_GSCALE,0,EPI_BLEND,1><<<dim3(16,16,2),256>>>(jG1, jBL, p_h, x);
        gemm_one<EPI_NONE,1><<<dim3(48,16),256>>>(jQK, nullptr, nullptr);
        k_attn<<<dim3(4,BHN),256,ATT_SMEM>>>();
        gemm_one<EPI_NONE,0><<<dim3(16,16),256>>>(jPH, nullptr, nullptr);
        k_ln<<<NTOK,256>>>(lng, lnb);
        k_fin<<<1,1>>>(i);
    }

    k_copy<<<(unsigned)((NHD+255)/256),256>>>(p_h, out, NHD);
    (void)in_sizes; (void)n_in; (void)out_size;
}

// round 7
// speedup vs baseline: 2.6276x; 1.0013x over previous
#include <cuda_runtime.h>
#include <cuda_bf16.h>
#include <math.h>
#include <stdint.h>

// ---------------- problem constants ----------------
#define BB 4
#define SS 512
#define DD 1024
#define HH 16
#define DHD 64
#define DQ 256
#define NTOK (BB*SS)            // 2048
#define BHN (BB*HH)             // 64
#define MIN_STEPS 4
#define MAX_STEPS 12

typedef __nv_bfloat16 bf16;

// ---------------- device state ----------------
__device__ int    g_act;
__device__ int    g_active;
__device__ int    g_num_steps;
__device__ float  g_gw0;
__device__ double g_red[2];

// fp32 buffers
__device__ float g_h   [NTOK*DD];
__device__ float g_G1  [NTOK*DD];
__device__ float g_phi [NTOK*DD];
__device__ float g_bqkv[3*DD];
__device__ float g_pool[BB*DD];
__device__ float g_sph [BB*DQ];

// split bf16 planes (hi / lo)
__device__ bf16 g_catH [NTOK*2*DD], g_catL [NTOK*2*DD];     // [h | x]
__device__ bf16 g_T1H  [NTOK*DQ],   g_T1L  [NTOK*DQ];
__device__ bf16 g_T2H  [NTOK*DQ],   g_T2L  [NTOK*DQ];
__device__ bf16 g_blnH [NTOK*DD],   g_blnL [NTOK*DD];
__device__ bf16 g_qkvH [NTOK*3*DD], g_qkvL [NTOK*3*DD];
__device__ bf16 g_ctxH [NTOK*DD],   g_ctxL [NTOK*DD];
// weight planes
__device__ bf16 g_w1H [DQ*DD],    g_w1L [DQ*DD];
__device__ bf16 g_w2H [DD*DQ],    g_w2L [DD*DQ];
__device__ bf16 g_iw1H[DQ*2*DD],  g_iw1L[DQ*2*DD];
__device__ bf16 g_iw2H[DD*DQ],    g_iw2L[DD*DQ];
__device__ bf16 g_wqH [3*DD*DD],  g_wqL [3*DD*DD];
__device__ bf16 g_woH [DD*DD],    g_woL [DD*DD];

// ---------------- scalar helpers ----------------
__device__ __forceinline__ float gelu_f(float v){ return 0.5f*v*(1.0f+erff(v*0.70710678118654752f)); }
__device__ __forceinline__ float sig_f (float v){ return 1.0f/(1.0f+__expf(-v)); }

__device__ __forceinline__ uint32_t pack_hi(float v0, float v1, float& r0, float& r1){
    bf16 h0 = __float2bfloat16(v0), h1 = __float2bfloat16(v1);
    r0 = v0 - __bfloat162float(h0);
    r1 = v1 - __bfloat162float(h1);
    return (uint32_t)__bfloat16_as_ushort(h0) | ((uint32_t)__bfloat16_as_ushort(h1) << 16);
}
__device__ __forceinline__ uint32_t pack_lo(float r0, float r1){
    return (uint32_t)__bfloat16_as_ushort(__float2bfloat16(r0)) |
           ((uint32_t)__bfloat16_as_ushort(__float2bfloat16(r1)) << 16);
}

template<typename T>
__device__ __forceinline__ T blockReduceSum(T v){
    static __shared__ T sh[32];
    int lane = threadIdx.x & 31, w = threadIdx.x >> 5;
    #pragma unroll
    for (int o = 16; o; o >>= 1) v += __shfl_down_sync(0xffffffffu, v, o);
    __syncthreads();
    if (lane == 0) sh[w] = v;
    __syncthreads();
    T r = (T)0;
    if (w == 0){
        int nw = (blockDim.x + 31) >> 5;
        r = (lane < nw) ? sh[lane] : (T)0;
        #pragma unroll
        for (int o = 16; o; o >>= 1) r += __shfl_down_sync(0xffffffffu, r, o);
    }
    return r;
}

__device__ __forceinline__ uint32_t s2u(const void* p){
    uint32_t a;
    asm("{ .reg .u64 t; cvta.to.shared.u64 t, %1; cvt.u32.u64 %0, t; }" : "=r"(a) : "l"(p));
    return a;
}
#define CPA16(d,s) asm volatile("cp.async.cg.shared.global [%0], [%1], 16;\n" :: "r"(d), "l"(s))
#define CPCOMMIT() asm volatile("cp.async.commit_group;\n" ::: "memory")
__device__ __forceinline__ void cpwait1(){ asm volatile("cp.async.wait_group 1;\n" ::: "memory"); }
__device__ __forceinline__ void cpwait0(){ asm volatile("cp.async.wait_group 0;\n" ::: "memory"); }

__device__ __forceinline__ void mma16816(float* c, const uint32_t* a, const uint32_t* b){
    asm volatile(
        "mma.sync.aligned.m16n8k16.row.col.f32.bf16.bf16.f32 "
        "{%0,%1,%2,%3}, {%4,%5,%6,%7}, {%8,%9}, {%0,%1,%2,%3};\n"
        : "+f"(c[0]), "+f"(c[1]), "+f"(c[2]), "+f"(c[3])
        : "r"(a[0]), "r"(a[1]), "r"(a[2]), "r"(a[3]), "r"(b[0]), "r"(b[1]));
}
__device__ __forceinline__ void ldsm4(uint32_t* r, uint32_t addr){
    asm volatile("ldmatrix.sync.aligned.m8n8.x4.shared.b16 {%0,%1,%2,%3}, [%4];"
        : "=r"(r[0]), "=r"(r[1]), "=r"(r[2]), "=r"(r[3]) : "r"(addr));
}
__device__ __forceinline__ void ldsm4t(uint32_t* r, uint32_t addr){
    asm volatile("ldmatrix.sync.aligned.m8n8.x4.trans.shared.b16 {%0,%1,%2,%3}, [%4];"
        : "=r"(r[0]), "=r"(r[1]), "=r"(r[2]), "=r"(r[3]) : "r"(addr));
}

// ---------------- pipelined split-bf16 HMMA NT GEMM core -------------------
enum { EPI_NONE=0, EPI_GELU=1, EPI_BLEND=3, EPI_GSCALE=4 };

struct GemmJob {
    int K;
    const bf16 *Ah, *Al; int lda;
    const bf16 *Bh, *Bl; int ldb;
    float* Cf; bf16 *Ch, *Cl; int ldc;
    const float* bias;
};

#define GBM 128
#define GBN 64
#define GBK 32
#define GLDK 40
#define STG_BYTES 30720
#define OFF_AL 10240u
#define OFF_BH 20480u
#define OFF_BL 25600u

template<int EPI,int WM>
__device__ __forceinline__ void gemm_core(const GemmJob J, char* buf,
                                          const float* Hp, const float* Xp)
{
    const int tid  = threadIdx.x;
    const int lane = tid & 31;
    const int wid  = tid >> 5;
    const int wm   = wid >> 1;
    const int wn   = wid & 1;
    const int g    = lane >> 2;
    const int q    = lane & 3;
    const int rm = blockIdx.y * GBM;
    const int cn = blockIdx.x * GBN;
    const uint32_t sb = s2u(buf);

    // ldmatrix lane geometry (elements)
    const int aRow = wm*32 + (lane & 15);
    const int aK   = (lane >> 4) << 3;
    const int bRow = wn*32 + ((lane >> 4) << 3) + (lane & 7);
    const int bK   = ((lane >> 3) & 1) << 3;

    auto stg = [&](int st, int kt){
        uint32_t sa = sb + (uint32_t)st * STG_BYTES;
        #pragma unroll
        for (int it=0; it<2; it++){
            int idx = tid + it*256;
            int row = idx >> 2;
            int c8  = (idx & 3) * 8;
            size_t go = (size_t)(rm+row)*J.lda + kt + c8;
            uint32_t d = sa + (uint32_t)(row*GLDK + c8)*2;
            CPA16(d,          J.Ah + go);
            CPA16(d + OFF_AL, J.Al + go);
        }
        {
            int row = tid >> 2;
            int c8  = (tid & 3) * 8;
            size_t go = (size_t)(cn+row)*J.ldb + kt + c8;
            uint32_t d = sa + OFF_BH + (uint32_t)(row*GLDK + c8)*2;
            CPA16(d,                    J.Bh + go);
            CPA16(d + (OFF_BL-OFF_BH),  J.Bl + go);
        }
        CPCOMMIT();
    };

    float acc[2][4][4];
    #pragma unroll
    for (int i=0;i<2;i++)
        #pragma unroll
        for (int j=0;j<4;j++)
            #pragma unroll
            for (int l=0;l<4;l++) acc[i][j][l] = 0.0f;

    const int niter = J.K / GBK;
    stg(0, 0);
    stg(1, GBK);

    for (int i=0; i<niter; i++){
        const int st = i & 1;
        const uint32_t sAh = sb + (uint32_t)st*STG_BYTES;
        const uint32_t sAl = sAh + OFF_AL;
        const uint32_t sBh = sAh + OFF_BH;
        const uint32_t sBl = sAh + OFF_BL;

        if (i+1 < niter) cpwait1(); else cpwait0();
        __syncthreads();

        #pragma unroll
        for (int ks=0; ks<2; ks++){
            const int ko = ks*16;
            uint32_t aH[2][4], aL[2][4], bH[2][4], bL[2][4];
            #pragma unroll
            for (int ma=0; ma<2; ma++){
                uint32_t off = (uint32_t)((aRow + ma*16)*GLDK + ko + aK)*2;
                ldsm4(aH[ma], sAh + off);
                ldsm4(aL[ma], sAl + off);
            }
            #pragma unroll
            for (int g2=0; g2<2; g2++){
                uint32_t off = (uint32_t)((bRow + g2*16)*GLDK + ko + bK)*2;
                ldsm4(bH[g2], sBh + off);
                ldsm4(bL[g2], sBl + off);
            }
            #pragma unroll
            for (int ma=0; ma<2; ma++)
                #pragma unroll
                for (int na=0; na<4; na++){
                    const uint32_t* bh = &bH[na>>1][(na&1)*2];
                    const uint32_t* bl = &bL[na>>1][(na&1)*2];
                    mma16816(acc[ma][na], aH[ma], bh);
                    mma16816(acc[ma][na], aH[ma], bl);
                    mma16816(acc[ma][na], aL[ma], bh);
                }
        }
        __syncthreads();
        if (i+2 < niter) stg(st, (i+2)*GBK);
    }

    // epilogue
    #pragma unroll
    for (int ma=0; ma<2; ma++){
        int r0 = rm + wm*32 + ma*16 + g;
        #pragma unroll
        for (int na=0; na<4; na++){
            int c = cn + wn*32 + na*8 + q*2;
            #pragma unroll
            for (int hrow=0; hrow<2; hrow++){
                int r = r0 + hrow*8;
                long long gi = (long long)r*J.ldc + c;
                float v[2];
                #pragma unroll
                for (int e=0; e<2; e++){
                    float t = acc[ma][na][hrow*2+e];
                    if (J.bias) t += J.bias[c+e];
                    if      (EPI==EPI_GELU)   t = gelu_f(t);
                    else if (EPI==EPI_GSCALE) t = sig_f(t) * g_gw0;
                    else if (EPI==EPI_BLEND){
                        float s = sig_f(t);
                        t = s*Hp[gi+e] + (1.0f - s)*Xp[gi+e];
                    }
                    v[e] = t;
                }
                if (WM == 0){
                    J.Cf[gi] = v[0]; J.Cf[gi+1] = v[1];
                } else {
                    float r0f, r1f;
                    uint32_t ph = pack_hi(v[0], v[1], r0f, r1f);
                    uint32_t pl = pack_lo(r0f, r1f);
                    *(uint32_t*)&J.Ch[gi] = ph;
                    *(uint32_t*)&J.Cl[gi] = pl;
                }
            }
        }
    }
}

template<int EPI,int WM>
__global__ void __launch_bounds__(256)
gemm_one(GemmJob J, const float* Hp, const float* Xp){
    if (g_act == 0) return;
    __shared__ char buf[2*STG_BYTES];
    gemm_core<EPI,WM>(J, buf, Hp, Xp);
}

template<int E0,int W0,int E1,int W1>
__global__ void __launch_bounds__(256)
gemm_dual(GemmJob J0, GemmJob J1, const float* Hp, const float* Xp){
    if (g_act == 0) return;
    __shared__ char buf[2*STG_BYTES];
    if (blockIdx.z == 0) gemm_core<E0,W0>(J0, buf, Hp, Xp);
    else                 gemm_core<E1,W1>(J1, buf, Hp, Xp);
}

// ---------------- fused flash attention (ldmatrix everywhere) -------------
// smem: Qh 0 (18432) Ql 18432 | Kh 36864(9216) Kl 46080 | Ph 36864 (18432, reuses K)
//       Vh 55296(9216) Vl 64512 | Pl 73728(18432) | floats 92160
#define LDQ 72
#define ATT_SMEM (92160 + 3072)
__global__ void __launch_bounds__(256) k_attn(void){
    if (g_act == 0) return;
    extern __shared__ char sm_[];
    bf16* Qh = (bf16*)(sm_);
    bf16* Ql = (bf16*)(sm_ + 18432);
    bf16* Kh = (bf16*)(sm_ + 36864);
    bf16* Kl = (bf16*)(sm_ + 46080);
    bf16* Ph = (bf16*)(sm_ + 36864);
    bf16* Vh = (bf16*)(sm_ + 55296);
    bf16* Vl = (bf16*)(sm_ + 64512);
    bf16* Pl = (bf16*)(sm_ + 73728);
    float* pm  = (float*)(sm_ + 92160);
    float* ps  = pm + 256;
    float* m_s = ps + 256;
    float* l_s = m_s + 128;

    const int tid  = threadIdx.x;
    const int lane = tid & 31;
    const int wid  = tid >> 5;
    const int wm   = wid >> 1;
    const int wn   = wid & 1;
    const int g    = lane >> 2;
    const int q    = lane & 3;

    const int qt = blockIdx.x;
    const int bh = blockIdx.y;
    const int b  = bh >> 4, hh = bh & 15;
    const long long tb = (long long)b*SS + qt*128;
    const int qoff = hh*64;

    const uint32_t sQh = s2u(sm_), sQl = sQh + 18432u;
    const uint32_t sKh = sQh + 36864u, sKl = sQh + 46080u;
    const uint32_t sPh = sQh + 36864u, sPl = sQh + 73728u;
    const uint32_t sVh = sQh + 55296u, sVl = sQh + 64512u;

    // ldmatrix lane geometry
    const int aRow = wm*32 + (lane & 15);           // A-type (Q, P)
    const int aK   = (lane >> 4) << 3;
    const int bRow = wn*32 + ((lane >> 4) << 3) + (lane & 7);   // B-type (K)
    const int bK   = ((lane >> 3) & 1) << 3;
    const int vT   = (lane & 7) + (((lane >> 3) & 1) << 3);     // B-trans (V)
    const int vD   = wn*32 + ((lane >> 4) << 3);

    if (tid < 128){ m_s[tid] = -1e30f; l_s[tid] = 0.0f; }

    #pragma unroll
    for (int it=0; it<4; it++){
        int idx = tid + it*256;
        int r = idx >> 3, c8 = (idx & 7)*8;
        long long go = (tb+r)*3072 + qoff + c8;
        *(uint4*)&Qh[r*LDQ + c8] = *(const uint4*)&g_qkvH[go];
        *(uint4*)&Ql[r*LDQ + c8] = *(const uint4*)&g_qkvL[go];
    }

    float acc_o[2][4][4];
    #pragma unroll
    for (int i=0;i<2;i++)
        #pragma unroll
        for (int j=0;j<4;j++)
            #pragma unroll
            for (int l=0;l<4;l++) acc_o[i][j][l]=0.0f;

    for (int kt = 0; kt < 8; kt++){
        __syncthreads();   // prev PV done (P reuses K region), Q staged (iter 0)
        const long long tk = (long long)b*SS + kt*64;
        #pragma unroll
        for (int it=0; it<2; it++){
            int idx = tid + it*256;
            int r = idx >> 3, c8 = (idx & 7)*8;
            long long goK = (tk+r)*3072 + 1024 + qoff + c8;
            long long goV = (tk+r)*3072 + 2048 + qoff + c8;
            *(uint4*)&Kh[r*LDQ + c8] = *(const uint4*)&g_qkvH[goK];
            *(uint4*)&Kl[r*LDQ + c8] = *(const uint4*)&g_qkvL[goK];
            *(uint4*)&Vh[r*LDQ + c8] = *(const uint4*)&g_qkvH[goV];
            *(uint4*)&Vl[r*LDQ + c8] = *(const uint4*)&g_qkvL[goV];
        }
        __syncthreads();

        // ---- S = Q @ K^T
        float acc_s[2][4][4];
        #pragma unroll
        for (int i=0;i<2;i++)
            #pragma unroll
            for (int j=0;j<4;j++)
                #pragma unroll
                for (int l=0;l<4;l++) acc_s[i][j][l]=0.0f;

        #pragma unroll
        for (int ko=0; ko<64; ko+=16){
            uint32_t aH[2][4], aL[2][4], bH[2][4], bL[2][4];
            #pragma unroll
            for (int ma=0; ma<2; ma++){
                uint32_t off = (uint32_t)((aRow + ma*16)*LDQ + ko + aK)*2;
                ldsm4(aH[ma], sQh + off);
                ldsm4(aL[ma], sQl + off);
            }
            #pragma unroll
            for (int g2=0; g2<2; g2++){
                uint32_t off = (uint32_t)((bRow + g2*16)*LDQ + ko + bK)*2;
                ldsm4(bH[g2], sKh + off);
                ldsm4(bL[g2], sKl + off);
            }
            #pragma unroll
            for (int ma=0; ma<2; ma++)
                #pragma unroll
                for (int na=0; na<4; na++){
                    const uint32_t* bhp = &bH[na>>1][(na&1)*2];
                    const uint32_t* blp = &bL[na>>1][(na&1)*2];
                    mma16816(acc_s[ma][na], aH[ma], bhp);
                    mma16816(acc_s[ma][na], aH[ma], blp);
                    mma16816(acc_s[ma][na], aL[ma], bhp);
                }
        }
        #pragma unroll
        for (int i=0;i<2;i++)
            #pragma unroll
            for (int j=0;j<4;j++)
                #pragma unroll
                for (int l=0;l<4;l++) acc_s[i][j][l] *= 0.125f;

        // ---- online softmax
        float rmx[2][2];
        #pragma unroll
        for (int ma=0; ma<2; ma++)
            #pragma unroll
            for (int rr=0; rr<2; rr++){
                float m = -1e30f;
                #pragma unroll
                for (int na=0; na<4; na++){
                    m = fmaxf(m, acc_s[ma][na][rr*2]);
                    m = fmaxf(m, acc_s[ma][na][rr*2+1]);
                }
                m = fmaxf(m, __shfl_xor_sync(0xffffffffu, m, 1));
                m = fmaxf(m, __shfl_xor_sync(0xffffffffu, m, 2));
                rmx[ma][rr] = m;
            }
        if (q == 0){
            #pragma unroll
            for (int ma=0; ma<2; ma++)
                #pragma unroll
                for (int rr=0; rr<2; rr++)
                    pm[wn*128 + wm*32 + ma*16 + rr*8 + g] = rmx[ma][rr];
        }
        __syncthreads();   // also: all S-MMA reads of K done before P overwrites it

        float mnew[2][2], sc[2][2];
        #pragma unroll
        for (int ma=0; ma<2; ma++)
            #pragma unroll
            for (int rr=0; rr<2; rr++){
                int r = wm*32 + ma*16 + rr*8 + g;
                float mo = m_s[r];
                float mn = fmaxf(mo, fmaxf(pm[r], pm[128+r]));
                mnew[ma][rr] = mn;
                sc[ma][rr] = __expf(mo - mn);
            }

        float rsm[2][2] = {{0,0},{0,0}};
        #pragma unroll
        for (int ma=0; ma<2; ma++)
            #pragma unroll
            for (int na=0; na<4; na++)
                #pragma unroll
                for (int e=0; e<4; e++){
                    int rr = e >> 1;
                    float p = __expf(acc_s[ma][na][e] - mnew[ma][rr]);
                    acc_s[ma][na][e] = p;
                    rsm[ma][rr] += p;
                }
        #pragma unroll
        for (int ma=0; ma<2; ma++)
            #pragma unroll
            for (int rr=0; rr<2; rr++){
                float s = rsm[ma][rr];
                s += __shfl_xor_sync(0xffffffffu, s, 1);
                s += __shfl_xor_sync(0xffffffffu, s, 2);
                rsm[ma][rr] = s;
            }
        if (q == 0){
            #pragma unroll
            for (int ma=0; ma<2; ma++)
                #pragma unroll
                for (int rr=0; rr<2; rr++)
                    ps[wn*128 + wm*32 + ma*16 + rr*8 + g] = rsm[ma][rr];
        }

        // write P split planes
        #pragma unroll
        for (int ma=0; ma<2; ma++){
            int r0 = wm*32 + ma*16 + g;
            #pragma unroll
            for (int na=0; na<4; na++){
                int c = wn*32 + na*8 + q*2;
                #pragma unroll
                for (int rr=0; rr<2; rr++){
                    int r = r0 + rr*8;
                    float l0, l1;
                    uint32_t phv = pack_hi(acc_s[ma][na][rr*2], acc_s[ma][na][rr*2+1], l0, l1);
                    uint32_t plv = pack_lo(l0, l1);
                    *(uint32_t*)&Ph[r*LDQ + c] = phv;
                    *(uint32_t*)&Pl[r*LDQ + c] = plv;
                }
            }
        }
        #pragma unroll
        for (int ma=0; ma<2; ma++)
            #pragma unroll
            for (int na=0; na<4; na++)
                #pragma unroll
                for (int e=0; e<4; e++) acc_o[ma][na][e] *= sc[ma][e>>1];
        __syncthreads();

        if (wn == 0 && q == 0){
            #pragma unroll
            for (int ma=0; ma<2; ma++)
                #pragma unroll
                for (int rr=0; rr<2; rr++){
                    int r = wm*32 + ma*16 + rr*8 + g;
                    l_s[r] = l_s[r]*sc[ma][rr] + ps[r] + ps[128+r];
                    m_s[r] = mnew[ma][rr];
                }
        }

        // ---- O += P @ V  (V via ldmatrix.trans from natural [t][d] layout)
        #pragma unroll
        for (int ko=0; ko<64; ko+=16){
            uint32_t aH[2][4], aL[2][4], bH[2][4], bL[2][4];
            #pragma unroll
            for (int ma=0; ma<2; ma++){
                uint32_t off = (uint32_t)((aRow + ma*16)*LDQ + ko + aK)*2;
                ldsm4(aH[ma], sPh + off);
                ldsm4(aL[ma], sPl + off);
            }
            #pragma unroll
            for (int g2=0; g2<2; g2++){
                uint32_t off = (uint32_t)((ko + vT)*LDQ + vD + g2*16 + ((lane>>4)<<3)*0)*2;
                // columns: vD already includes (lane>>4)<<3; add g2*16
                ldsm4t(bH[g2], sVh + off);
                ldsm4t(bL[g2], sVl + off);
            }
            #pragma unroll
            for (int ma=0; ma<2; ma++)
                #pragma unroll
                for (int na=0; na<4; na++){
                    const uint32_t* bhp = &bH[na>>1][(na&1)*2];
                    const uint32_t* blp = &bL[na>>1][(na&1)*2];
                    mma16816(acc_o[ma][na], aH[ma], bhp);
                    mma16816(acc_o[ma][na], aH[ma], blp);
                    mma16816(acc_o[ma][na], aL[ma], bhp);
                }
        }
    }
    __syncthreads();

    // epilogue
    #pragma unroll
    for (int ma=0; ma<2; ma++){
        int r0 = wm*32 + ma*16 + g;
        #pragma unroll
        for (int na=0; na<4; na++){
            int c = wn*32 + na*8 + q*2;
            #pragma unroll
            for (int rr=0; rr<2; rr++){
                int r = r0 + rr*8;
                float inv = 1.0f / l_s[r];
                float o0 = acc_o[ma][na][rr*2]   * inv;
                float o1 = acc_o[ma][na][rr*2+1] * inv;
                long long gi = (tb + r)*DD + qoff + c;
                float l0, l1;
                uint32_t phv = pack_hi(o0, o1, l0, l1);
                uint32_t plv = pack_lo(l0, l1);
                *(uint32_t*)&g_ctxH[gi] = phv;
                *(uint32_t*)&g_ctxL[gi] = plv;
            }
        }
    }
}

// ---------------- small kernels ----------------
__global__ void k_copy(const float* __restrict__ s, float* __restrict__ d, long long n){
    long long i = (long long)blockIdx.x*blockDim.x + threadIdx.x;
    if (i < n) d[i] = s[i];
}

__global__ void k_split(const float* __restrict__ s, bf16* __restrict__ dh,
                        bf16* __restrict__ dl, long long n){
    long long i = (long long)blockIdx.x*blockDim.x + threadIdx.x;
    if (i >= n) return;
    float v = s[i];
    bf16 h = __float2bfloat16(v);
    dh[i] = h;
    dl[i] = __float2bfloat16(v - __bfloat162float(h));
}

__global__ void k_split_cat(const float* __restrict__ s, int colOff){
    long long i = (long long)blockIdx.x*blockDim.x + threadIdx.x;
    if (i >= (long long)NTOK*DD) return;
    int t = (int)(i >> 10), j = (int)(i & 1023);
    float v = s[i];
    bf16 h = __float2bfloat16(v);
    long long di = (long long)t*2*DD + colOff + j;
    g_catH[di] = h;
    g_catL[di] = __float2bfloat16(v - __bfloat162float(h));
}

__global__ void k_pool(const float* __restrict__ h){
    int i = blockIdx.x*blockDim.x + threadIdx.x;
    if (i >= BB*DD) return;
    int b = i / DD, d = i % DD;
    const float* p = h + (long long)b*SS*DD + d;
    float s = 0.0f;
    for (int t=0;t<SS;t++) s += p[(long long)t*DD];
    g_pool[i] = s * (1.0f/(float)SS);
}

__global__ void k_sp1(const float* __restrict__ w1, const float* __restrict__ b1){
    int i = blockIdx.x*blockDim.x + threadIdx.x;
    if (i >= BB*DQ) return;
    int b = i / DQ, j = i % DQ;
    const float* p = g_pool + b*DD;
    const float* w = w1 + (long long)j*DD;
    float s = b1[j];
    for (int d=0; d<DD; d++) s = fmaf(p[d], w[d], s);
    g_sph[i] = gelu_f(s);
}

__global__ void k_init(const float* __restrict__ w2, const float* __restrict__ b2,
                       const float* __restrict__ gl){
    if (threadIdx.x != 0) return;
    float m = 0.0f;
    for (int b=0;b<BB;b++){
        float s = b2[0];
        for (int j=0;j<DQ;j++) s = fmaf(g_sph[b*DQ+j], w2[j], s);
        m += 1.0f/(1.0f + expf(-s));
    }
    m *= 1.0f/(float)BB;
    int ns = MIN_STEPS + (int)floorf(m * (float)(MAX_STEPS - MIN_STEPS));
    if (ns > MAX_STEPS) ns = MAX_STEPS;
    g_num_steps = ns;
    g_active = 1;
    float e0 = expf(gl[0]), e1 = expf(gl[1]), e2 = expf(gl[2]);
    g_gw0 = e0/(e0+e1+e2);
}

__global__ void k_begin(int i){
    if (threadIdx.x == 0){
        g_act = (g_active && (i < g_num_steps)) ? 1 : 0;
        g_red[0] = 0.0; g_red[1] = 0.0;
    }
}

__global__ void k_ln(const float* __restrict__ lg, const float* __restrict__ lb){
    if (g_act == 0) return;
    long long off = (long long)blockIdx.x * DD;
    int t = threadIdx.x;
    float u[4], hv[4];
    float sm = 0.0f;
    #pragma unroll
    for (int j=0;j<4;j++){
        int idx = t + j*256;
        hv[j] = g_h[off+idx];
        u[j]  = fmaf(g_G1[off+idx], g_phi[off+idx], hv[j]);
        sm += u[j];
    }
    sm = blockReduceSum<float>(sm);
    __shared__ float s_mean, s_inv;
    if (t==0) s_mean = sm * (1.0f/(float)DD);
    __syncthreads();
    float mean = s_mean, vs = 0.0f;
    #pragma unroll
    for (int j=0;j<4;j++){ float d = u[j]-mean; vs += d*d; }
    vs = blockReduceSum<float>(vs);
    if (t==0) s_inv = rsqrtf(vs*(1.0f/(float)DD) + 1e-5f);
    __syncthreads();
    float inv = s_inv;
    double dq = 0.0, hq = 0.0;
    long long cbase = (long long)blockIdx.x * 2*DD;
    #pragma unroll
    for (int j=0;j<4;j++){
        int idx = t + j*256;
        float y = (u[j]-mean)*inv*lg[idx] + lb[idx];
        g_h[off+idx] = y;
        bf16 hb = __float2bfloat16(y);
        g_catH[cbase+idx] = hb;
        g_catL[cbase+idx] = __float2bfloat16(y - __bfloat162float(hb));
        float df = y - hv[j];
        dq += (double)df*(double)df;
        hq += (double)hv[j]*(double)hv[j];
    }
    dq = blockReduceSum<double>(dq);
    hq = blockReduceSum<double>(hq);
    if (t==0){ atomicAdd(&g_red[0], dq); atomicAdd(&g_red[1], hq); }
}

__global__ void k_fin(int i){
    if (threadIdx.x != 0) return;
    if (g_act == 0){ g_active = 0; return; }
    double res = sqrt(g_red[0]) / (sqrt(g_red[1]) + 1e-8);
    g_active = ((i >= MIN_STEPS) && (res < 1e-4)) ? 0 : 1;
}

// ---------------- host ----------------
template<typename T>
static T* dptr(const void* symbol){
    void* p = nullptr;
    cudaGetSymbolAddress(&p, symbol);
    return (T*)p;
}

extern "C" void kernel_launch(void* const* d_in, const int* in_sizes, int n_in,
                              void* d_out, int out_size)
{
    const float* h     = (const float*)d_in[0];
    const float* x     = (const float*)d_in[1];
    const float* ig_w1 = (const float*)d_in[2];
    const float* ig_b1 = (const float*)d_in[3];
    const float* ig_w2 = (const float*)d_in[4];
    const float* ig_b2 = (const float*)d_in[5];
    const float* wq    = (const float*)d_in[6];
    const float* bq    = (const float*)d_in[7];
    const float* wk    = (const float*)d_in[8];
    const float* bk    = (const float*)d_in[9];
    const float* wv    = (const float*)d_in[10];
    const float* bv    = (const float*)d_in[11];
    const float* wo    = (const float*)d_in[12];
    const float* bo    = (const float*)d_in[13];
    const float* g1w1  = (const float*)d_in[14];
    const float* g1b1  = (const float*)d_in[15];
    const float* g1w2  = (const float*)d_in[16];
    const float* g1b2  = (const float*)d_in[17];
    const float* gl    = (const float*)d_in[18];
    const float* lng   = (const float*)d_in[19];
    const float* lnb   = (const float*)d_in[20];
    const float* spw1  = (const float*)d_in[21];
    const float* spb1  = (const float*)d_in[22];
    const float* spw2  = (const float*)d_in[23];
    const float* spb2  = (const float*)d_in[24];
    float* out = (float*)d_out;

    float* p_h    = dptr<float>(g_h);
    float* p_G1   = dptr<float>(g_G1);
    float* p_phi  = dptr<float>(g_phi);
    float* p_bqkv = dptr<float>(g_bqkv);
    bf16 *p_catH = dptr<bf16>(g_catH), *p_catL = dptr<bf16>(g_catL);
    bf16 *p_T1H  = dptr<bf16>(g_T1H),  *p_T1L  = dptr<bf16>(g_T1L);
    bf16 *p_T2H  = dptr<bf16>(g_T2H),  *p_T2L  = dptr<bf16>(g_T2L);
    bf16 *p_blnH = dptr<bf16>(g_blnH), *p_blnL = dptr<bf16>(g_blnL);
    bf16 *p_qkvH = dptr<bf16>(g_qkvH), *p_qkvL = dptr<bf16>(g_qkvL);
    bf16 *p_ctxH = dptr<bf16>(g_ctxH), *p_ctxL = dptr<bf16>(g_ctxL);
    bf16 *p_w1H  = dptr<bf16>(g_w1H),  *p_w1L  = dptr<bf16>(g_w1L);
    bf16 *p_w2H  = dptr<bf16>(g_w2H),  *p_w2L  = dptr<bf16>(g_w2L);
    bf16 *p_iw1H = dptr<bf16>(g_iw1H), *p_iw1L = dptr<bf16>(g_iw1L);
    bf16 *p_iw2H = dptr<bf16>(g_iw2H), *p_iw2L = dptr<bf16>(g_iw2L);
    bf16 *p_wqH  = dptr<bf16>(g_wqH),  *p_wqL  = dptr<bf16>(g_wqL);
    bf16 *p_woH  = dptr<bf16>(g_woH),  *p_woL  = dptr<bf16>(g_woL);

    const long long NHD = (long long)NTOK*DD;
    const long long W1  = (long long)DD*DD;

    cudaFuncSetAttribute(k_attn, cudaFuncAttributeMaxDynamicSharedMemorySize, ATT_SMEM);

    // ---- setup
    k_copy<<<(unsigned)((NHD+255)/256),256>>>(h, p_h, NHD);
    k_split_cat<<<(unsigned)((NHD+255)/256),256>>>(h, 0);
    k_split_cat<<<(unsigned)((NHD+255)/256),256>>>(x, DD);
    k_split<<<(DQ*DD+255)/256,256>>>(g1w1,  p_w1H,  p_w1L,  DQ*DD);
    k_split<<<(DD*DQ+255)/256,256>>>(g1w2,  p_w2H,  p_w2L,  DD*DQ);
    k_split<<<(DQ*2*DD+255)/256,256>>>(ig_w1, p_iw1H, p_iw1L, DQ*2*DD);
    k_split<<<(DD*DQ+255)/256,256>>>(ig_w2, p_iw2H, p_iw2L, DD*DQ);
    k_split<<<(unsigned)((W1+255)/256),256>>>(wq, p_wqH,        p_wqL,        W1);
    k_split<<<(unsigned)((W1+255)/256),256>>>(wk, p_wqH + W1,   p_wqL + W1,   W1);
    k_split<<<(unsigned)((W1+255)/256),256>>>(wv, p_wqH + 2*W1, p_wqL + 2*W1, W1);
    k_split<<<(unsigned)((W1+255)/256),256>>>(wo, p_woH, p_woL, W1);
    k_copy<<<4,256>>>(bq, p_bqkv,        DD);
    k_copy<<<4,256>>>(bk, p_bqkv +   DD, DD);
    k_copy<<<4,256>>>(bv, p_bqkv + 2*DD, DD);
    k_pool<<<(BB*DD+255)/256,256>>>(h);
    k_sp1 <<<(BB*DQ+255)/256,256>>>(spw1, spb1);
    k_init<<<1,32>>>(spw2, spb2, gl);

    GemmJob jT1 = { DD,   p_catH, p_catL, 2*DD, p_w1H,  p_w1L,  DD,   nullptr, p_T1H,  p_T1L,  DQ,   g1b1 };
    GemmJob jT2 = { 2*DD, p_catH, p_catL, 2*DD, p_iw1H, p_iw1L, 2*DD, nullptr, p_T2H,  p_T2L,  DQ,   ig_b1 };
    GemmJob jG1 = { DQ,   p_T1H,  p_T1L,  DQ,   p_w2H,  p_w2L,  DQ,   p_G1,    nullptr,nullptr,DD,   g1b2 };
    GemmJob jBL = { DQ,   p_T2H,  p_T2L,  DQ,   p_iw2H, p_iw2L, DQ,   nullptr, p_blnH, p_blnL, DD,   ig_b2 };
    GemmJob jQK = { DD,   p_blnH, p_blnL, DD,   p_wqH,  p_wqL,  DD,   nullptr, p_qkvH, p_qkvL, 3*DD, p_bqkv };
    GemmJob jPH = { DD,   p_ctxH, p_ctxL, DD,   p_woH,  p_woL,  DD,   p_phi,   nullptr,nullptr,DD,   bo };

    for (int i = 0; i < MAX_STEPS; i++){
        k_begin<<<1,32>>>(i);

        gemm_dual<EPI_GELU,1,EPI_GELU,1><<<dim3(4,16,2),256>>>(jT1, jT2, nullptr, nullptr);
        gemm_dual<EPI_GSCALE,0,EPI_BLEND,1><<<dim3(16,16,2),256>>>(jG1, jBL, p_h, x);
        gemm_one<EPI_NONE,1><<<dim3(48,16),256>>>(jQK, nullptr, nullptr);
        k_attn<<<dim3(4,BHN),256,ATT_SMEM>>>();
        gemm_one<EPI_NONE,0><<<dim3(16,16),256>>>(jPH, nullptr, nullptr);
        k_ln<<<NTOK,256>>>(lng, lnb);
        k_fin<<<1,1>>>(i);
    }

    k_copy<<<(unsigned)((NHD+255)/256),256>>>(p_h, out, NHD);
    (void)in_sizes; (void)n_in; (void)out_size;
}